// round 7
// baseline (speedup 1.0000x reference)
#include <cuda_runtime.h>
#include <math.h>

// ISDALoss_EM on GB300 — round 7.
#define A_DIM 128
#define PITCH 132
#define MAX_S 512
#define MAX_N 4096
#define MAX_C 128

__device__ float g_D[MAX_S * A_DIM];
__device__ float g_U[MAX_S * A_DIM];
__device__ float g_score[MAX_N * 8];
__device__ int   g_labels[MAX_N];
__device__ int   g_ccount[MAX_C];
__device__ int   g_clist[(size_t)MAX_C * MAX_N];

__device__ __forceinline__ void fma2(unsigned long long& d, unsigned long long a,
                                     unsigned long long b) {
    asm("fma.rn.f32x2 %0, %1, %2, %0;" : "+l"(d) : "l"(a), "l"(b));
}
__device__ __forceinline__ unsigned long long pack2(float lo, float hi) {
    unsigned long long r;
    asm("mov.b64 %0, {%1,%2};" : "=l"(r) : "f"(lo), "f"(hi));
    return r;
}
__device__ __forceinline__ float2 unpack2(unsigned long long v) {
    float2 f;
    asm("mov.b64 {%0,%1}, %2;" : "=f"(f.x), "=f"(f.y) : "l"(v));
    return f;
}

// labels: loss init + dtype detect + convert + per-class lists.
// Single block, 1024 threads; all counting via SMEM atomics.
__global__ void k_labels(const int* __restrict__ raw, int n,
                         float* out, int writeLoss) {
    __shared__ int odd_nz;
    __shared__ int scount[MAX_C];
    __shared__ int scursor[MAX_C];
    const int tid = threadIdx.x;
    if (tid == 0) {
        odd_nz = 0;
        if (writeLoss) out[0] = 0.0f;
    }
    if (tid < MAX_C) { scount[tid] = 0; scursor[tid] = 0; }
    __syncthreads();
    for (int i = tid; i < n / 2; i += 1024)
        if (raw[2 * i + 1] != 0) atomicOr(&odd_nz, 1);
    __syncthreads();
    const bool is32 = (odd_nz != 0);
    for (int i = tid; i < n; i += 1024) {
        int c = is32 ? raw[i] : raw[2 * i];
        g_labels[i] = c;
        atomicAdd(&scount[c], 1);
    }
    __syncthreads();
    if (tid < MAX_C) g_ccount[tid] = scount[tid];
    for (int i = tid; i < n; i += 1024) {
        int c = g_labels[i];
        int p = atomicAdd(&scursor[c], 1);
        g_clist[(size_t)c * MAX_N + p] = i;
    }
}

// ---- fused: v, blocked Cholesky, D/U, in-smem transpose, class solves -------
__global__ __launch_bounds__(256, 2)
void k_fused(const float* __restrict__ sigma, const float* __restrict__ W,
             const float* __restrict__ F, const float* __restrict__ mu,
             int C, int K) {
    extern __shared__ float sh[];
    float* sA  = sh;                       // 128 * 132
    float* sW  = sA + A_DIM * PITCH;       // 128 * 33
    float* swl = sW + A_DIM * 33;          // 128
    float* sv  = swl + A_DIM;              // 128
    float* srd = sv + A_DIM;               // 128
    float* sdg = srd + A_DIM;              // 128
    float* sD  = sdg + A_DIM;              // 128
    float* sU  = sD + A_DIM;               // 128
    __shared__ float slogdet;

    const int s = blockIdx.x;
    const int cls = s / K;
    const int kk = s - cls * K;
    const int tid = threadIdx.x;
    const int wid = tid >> 5, lane = tid & 31;

    // ---- load Sigma (float4, coalesced), w_l; zero sD ----
    {
        const float4* src4 = reinterpret_cast<const float4*>(sigma + (size_t)s * A_DIM * A_DIM);
        for (int idx = tid; idx < A_DIM * 32; idx += 256) {
            int i = idx >> 5, f = idx & 31;
            *reinterpret_cast<float4*>(&sA[i * PITCH + 4 * f]) = src4[idx];
        }
        if (tid < A_DIM) { swl[tid] = W[cls * A_DIM + tid]; sD[tid] = 0.0f; }
    }
    __syncthreads();

    // ---- v = Sigma @ w_l (before factorization) ----
    if (tid < A_DIM) {
        float acc = 0.0f;
        #pragma unroll 8
        for (int b = 0; b < A_DIM; ++b) acc += sA[b * PITCH + tid] * swl[b];
        sv[tid] = acc;
    }
    __syncthreads();

    // ---- blocked Cholesky (NB = 32) ----
    for (int kb = 0; kb < A_DIM; kb += 32) {
        if (wid == 0) {
            float m[32];
            float* row = &sA[(kb + lane) * PITCH + kb];
            #pragma unroll
            for (int c = 0; c < 32; ++c) m[c] = row[c];
            #pragma unroll
            for (int j = 0; j < 32; ++j) {
                float dj = __shfl_sync(0xffffffffu, m[j], j);
                float l = m[j] * rsqrtf(dj);
                m[j] = l;
                #pragma unroll
                for (int p = j + 1; p < 32; ++p)
                    m[p] -= l * __shfl_sync(0xffffffffu, l, p);
            }
            #pragma unroll
            for (int c = 0; c < 32; ++c)
                if (c <= lane) row[c] = m[c];
            srd[kb + lane] = 1.0f / m[lane];
            sdg[kb + lane] = m[lane];
        }
        __syncthreads();

        const int R = A_DIM - kb - 32;
        if (R > 0) {
            if (tid < R) {
                const int row = kb + 32 + tid;
                float* pr = &sA[row * PITCH + kb];
                const float* pd = &sA[kb * PITCH + kb];
                float x[32];
                #pragma unroll
                for (int c = 0; c < 32; ++c) x[c] = pr[c];
                #pragma unroll
                for (int j = 0; j < 32; ++j) {
                    float a = x[j];
                    #pragma unroll
                    for (int p = 0; p < j; ++p) a -= x[p] * pd[j * PITCH + p];
                    x[j] = a * srd[kb + j];
                }
                #pragma unroll
                for (int c = 0; c < 32; ++c) pr[c] = x[c];
            }
            __syncthreads();

            const int nb = R >> 5;
            const int ntask = nb * (nb + 1);
            for (int task = wid; task < ntask; task += 8) {
                int b = 0, t = task;
                while (t >= 2 * b + 2) { t -= 2 * b + 2; ++b; }
                const int i  = kb + 32 + 32 * b + lane;
                const int j0 = kb + 32 + 16 * t;
                unsigned long long acc[16];
                #pragma unroll
                for (int q = 0; q < 16; ++q) acc[q] = 0ull;
                const float* pa = &sA[i * PITCH + kb];
                #pragma unroll
                for (int k = 0; k < 32; k += 4) {
                    ulonglong2 av = *reinterpret_cast<const ulonglong2*>(pa + k);
                    #pragma unroll
                    for (int q = 0; q < 16; ++q) {
                        ulonglong2 bv = *reinterpret_cast<const ulonglong2*>(
                            &sA[(j0 + q) * PITCH + kb + k]);
                        fma2(acc[q], av.x, bv.x);
                        fma2(acc[q], av.y, bv.y);
                    }
                }
                #pragma unroll
                for (int q = 0; q < 16; ++q) {
                    int col = j0 + q;
                    if (col <= i) {
                        float2 f = unpack2(acc[q]);
                        sA[i * PITCH + col] -= f.x + f.y;
                    }
                }
            }
            __syncthreads();
        }
    }

    // ---- zero strict upper triangle (row-contiguous writes); logdet ----
    for (int idx = tid; idx < A_DIM * A_DIM; idx += 256) {
        int i = idx >> 7, j = idx & 127;
        if (j > i) sA[i * PITCH + j] = 0.0f;
    }
    if (tid < 32) {
        float v = logf(sdg[tid]) + logf(sdg[tid + 32]) +
                  logf(sdg[tid + 64]) + logf(sdg[tid + 96]);
        #pragma unroll
        for (int o = 16; o; o >>= 1) v += __shfl_xor_sync(0xffffffffu, v, o);
        if (tid == 0) slogdet = 2.0f * v;
    }

    // ---- D_c = ||L^T w_c||^2 (register-tiled, packed-pair loads), U_c = v.w_c
    for (int g = 0; g < 4; ++g) {
        __syncthreads();
        for (int idx = tid; idx < 32 * 32; idx += 256) {
            int cc = idx >> 5, f = idx & 31;
            int c = 32 * g + cc;
            float4 wv = (c < C) ? reinterpret_cast<const float4*>(W + (size_t)c * A_DIM)[f]
                                : make_float4(0.f, 0.f, 0.f, 0.f);
            sW[(4 * f + 0) * 33 + cc] = wv.x;
            sW[(4 * f + 1) * 33 + cc] = wv.y;
            sW[(4 * f + 2) * 33 + cc] = wv.z;
            sW[(4 * f + 3) * 33 + cc] = wv.w;
        }
        __syncthreads();

        const int t = (g & 1) ? (7 - wid) : wid;
        const int j0 = 16 * t;
        unsigned long long acc[8];
        #pragma unroll
        for (int q = 0; q < 8; ++q) acc[q] = 0ull;
        float u = 0.0f;
        const bool doU = (t == 0);

        #pragma unroll 2
        for (int i = j0; i < A_DIM; ++i) {
            const ulonglong2* Lr = reinterpret_cast<const ulonglong2*>(&sA[i * PITCH + j0]);
            ulonglong2 p0 = Lr[0];
            ulonglong2 p1 = Lr[1];
            float wv = sW[i * 33 + lane];
            unsigned long long w2 = pack2(wv, wv);
            fma2(acc[0], p0.x, w2);
            fma2(acc[1], p0.y, w2);
            fma2(acc[2], p1.x, w2);
            fma2(acc[3], p1.y, w2);
            ulonglong2 p2 = Lr[2];
            ulonglong2 p3 = Lr[3];
            fma2(acc[4], p2.x, w2);
            fma2(acc[5], p2.y, w2);
            fma2(acc[6], p3.x, w2);
            fma2(acc[7], p3.y, w2);
            if (doU) u += sv[i] * wv;
        }
        unsigned long long d2 = 0ull;
        #pragma unroll
        for (int q = 0; q < 8; ++q) fma2(d2, acc[q], acc[q]);
        float2 dd = unpack2(d2);
        int c = 32 * g + lane;
        atomicAdd(&sD[c], dd.x + dd.y);
        if (doU) sU[c] = u;
    }
    __syncthreads();

    for (int c = tid; c < C; c += 256) {
        g_D[s * A_DIM + c] = sD[c];
        g_U[s * A_DIM + c] = sU[c];
    }

    // ---- transpose lower -> upper (dest-contiguous writes); stale lower is
    //      harmless: solve only consumes already-retired components from it.
    for (int idx = tid; idx < A_DIM * A_DIM; idx += 256) {
        int j = idx >> 7, i = idx & 127;
        if (i > j) sA[j * PITCH + i] = sA[i * PITCH + j];
    }
    __syncthreads();

    // ---- class-grouped solves: score = dist + logdet, 4 samples per warp ----
    const int cnt = g_ccount[cls];
    const float logd = slogdet;
    const float4* F4 = reinterpret_cast<const float4*>(F);
    const float4 mv = reinterpret_cast<const float4*>(mu)[(size_t)s * 32 + lane];

    for (int m0 = wid * 4; m0 < cnt; m0 += 32) {
        int n[4];
        bool has[4];
        #pragma unroll
        for (int r = 0; r < 4; ++r) {
            has[r] = (m0 + r) < cnt;
            n[r] = g_clist[(size_t)cls * MAX_N + (has[r] ? (m0 + r) : m0)];
        }
        float d[4][4], dist[4];
        #pragma unroll
        for (int r = 0; r < 4; ++r) {
            float4 fv = F4[(size_t)n[r] * 32 + lane];
            d[r][0] = fv.x - mv.x; d[r][1] = fv.y - mv.y;
            d[r][2] = fv.z - mv.z; d[r][3] = fv.w - mv.w;
            dist[r] = 0.0f;
        }
        #pragma unroll 4
        for (int j = 0; j < A_DIM; ++j) {
            float4 col = *reinterpret_cast<const float4*>(&sA[j * PITCH + 4 * lane]);
            float rdj = srd[j];
            int owner = j >> 2, q = j & 3;
            #pragma unroll
            for (int r = 0; r < 4; ++r) {
                float dq = (q == 0) ? d[r][0] : (q == 1) ? d[r][1]
                         : (q == 2) ? d[r][2] : d[r][3];
                float z = __shfl_sync(0xffffffffu, dq, owner) * rdj;
                dist[r] += z * z;
                d[r][0] -= col.x * z;
                d[r][1] -= col.y * z;
                d[r][2] -= col.z * z;
                d[r][3] -= col.w * z;
            }
        }
        if (lane == 0) {
            #pragma unroll
            for (int r = 0; r < 4; ++r)
                if (has[r]) g_score[n[r] * 8 + kk] = dist[r] + logd;
        }
    }
}

// ---------------- fused y = F W^T + b, argmin, aug, log-softmax, loss --------
// NB=16 (round-5 shape, measured 26 us) + in-place aug (reg relief).
#define NB 16
__global__ void k_yloss(const float* __restrict__ F, const float* __restrict__ W,
                        const float* __restrict__ bias, const float* __restrict__ ratioPtr,
                        float* __restrict__ yout, float* __restrict__ lossout,
                        int N, int C, int K, int writeLoss) {
    extern __shared__ float sh[];
    float* sWT = sh;                       // [128][C]
    float* sF  = sWT + A_DIM * C;          // [NB][128]
    float* sY  = sF + NB * A_DIM;          // [NB][C]  (y, then aug in-place)
    float* sB  = sY + NB * C;              // [C]
    const int tid = threadIdx.x;
    const int n0 = blockIdx.x * NB;

    for (int idx = tid; idx < C * A_DIM; idx += 256) {
        int c = idx >> 7, aa = idx & 127;
        sWT[aa * C + c] = W[idx];
    }
    for (int idx = tid; idx < NB * A_DIM; idx += 256) {
        int nl = idx >> 7;
        int n = n0 + nl;
        sF[idx] = (n < N) ? F[(size_t)n * A_DIM + (idx & 127)] : 0.0f;
    }
    for (int c = tid; c < C; c += 256) sB[c] = bias[c];
    __syncthreads();

    const int warp = tid >> 5, lane = tid & 31;
    const int nchunk = (C + 31) >> 5;

    for (int task = warp; task < NB * nchunk; task += 8) {
        int nl = task / nchunk;
        int c = (task - nl * nchunk) * 32 + lane;
        int n = n0 + nl;
        if (c < C && n < N) {
            float acc = sB[c];
            const float* f = sF + nl * A_DIM;
            #pragma unroll
            for (int aa = 0; aa < A_DIM; aa += 4) {
                float4 fv = *reinterpret_cast<const float4*>(f + aa);
                acc += fv.x * sWT[aa * C + c];
                acc += fv.y * sWT[(aa + 1) * C + c];
                acc += fv.z * sWT[(aa + 2) * C + c];
                acc += fv.w * sWT[(aa + 3) * C + c];
            }
            sY[nl * C + c] = acc;
            yout[(size_t)n * C + c] = acc;
        }
    }
    __syncthreads();

    const float hr = 0.5f * ratioPtr[0];
    for (int nl = warp; nl < NB; nl += 8) {
        int n = n0 + nl;
        if (n >= N) continue;
        int l = g_labels[n];
        const float* sc = g_score + n * 8;
        int k = 0;
        float best = sc[0];
        for (int kkk = 1; kkk < K; ++kkk) {
            float v = sc[kkk];
            if (v < best) { best = v; k = kkk; }
        }
        int s = l * K + k;
        const float* Dp = g_D + s * A_DIM;
        const float* Up = g_U + s * A_DIM;
        float ul = Up[l];
        float* aug = sY + nl * C;

        float mymax = -INFINITY;
        for (int m = 0; m < nchunk; ++m) {
            int c = lane + 32 * m;
            if (c < C) {
                float v = aug[c] + hr * (Dp[c] - 2.0f * Up[c] + ul);
                aug[c] = v;
                mymax = fmaxf(mymax, v);
            }
        }
        #pragma unroll
        for (int o = 16; o; o >>= 1)
            mymax = fmaxf(mymax, __shfl_xor_sync(0xffffffffu, mymax, o));
        __syncwarp();
        float sum = 0.0f;
        for (int m = 0; m < nchunk; ++m) {
            int c = lane + 32 * m;
            if (c < C) sum += expf(aug[c] - mymax);
        }
        #pragma unroll
        for (int o = 16; o; o >>= 1) sum += __shfl_xor_sync(0xffffffffu, sum, o);
        if (lane == 0 && writeLoss) {
            float lse = mymax + logf(sum);
            atomicAdd(lossout, (lse - aug[l]) / (float)N);
        }
    }
}

// ---------------- launch -----------------------------------------------------
extern "C" void kernel_launch(void* const* d_in, const int* in_sizes, int n_in,
                              void* d_out, int out_size) {
    const float* F     = (const float*)d_in[0];
    const float* W     = (const float*)d_in[1];
    const float* bias  = (const float*)d_in[2];
    const float* mu    = (const float*)d_in[4];
    const float* sigma = (const float*)d_in[5];
    const int*   lraw  = (const int*)d_in[6];
    const float* ratio = (const float*)d_in[7];

    const int C = in_sizes[2];
    const int K = in_sizes[3] / C;
    const int Ad = in_sizes[1] / C;
    const int N = in_sizes[0] / Ad;
    const int S = C * K;

    float* out = (float*)d_out;
    const int yoff = out_size - N * C;
    const int writeLoss = (yoff >= 1) ? 1 : 0;
    float* yout = out + (yoff > 0 ? yoff : 0);

    const int smem_fused = (A_DIM * PITCH + A_DIM * 33 + 6 * A_DIM) * 4;   // 87552
    const int smem_yl    = (A_DIM * C + NB * A_DIM + NB * C + C) * 4;      // 66192

    cudaFuncSetAttribute(k_fused, cudaFuncAttributeMaxDynamicSharedMemorySize, smem_fused);
    cudaFuncSetAttribute(k_yloss, cudaFuncAttributeMaxDynamicSharedMemorySize, smem_yl);

    k_labels<<<1, 1024>>>(lraw, N, out, writeLoss);
    k_fused<<<S, 256, smem_fused>>>(sigma, W, F, mu, C, K);
    k_yloss<<<(N + NB - 1) / NB, 256, smem_yl>>>(F, W, bias, ratio, yout, out,
                                                 N, C, K, writeLoss);
}

// round 8
// speedup vs baseline: 1.2138x; 1.2138x over previous
#include <cuda_runtime.h>
#include <math.h>

// ISDALoss_EM on GB300 — round 8: k_fused reverted verbatim to the measured-139.8
// round-5 version; k_labels from round 7 (smem atomics); k_yloss widened to 512 thr.
#define A_DIM 128
#define PITCH 132
#define MAX_S 512
#define MAX_N 4096
#define MAX_C 128

__device__ float g_D[MAX_S * A_DIM];
__device__ float g_U[MAX_S * A_DIM];
__device__ float g_score[MAX_N * 8];
__device__ int   g_labels[MAX_N];
__device__ int   g_ccount[MAX_C];
__device__ int   g_clist[(size_t)MAX_C * MAX_N];

__device__ __forceinline__ void fma2(unsigned long long& d, unsigned long long a,
                                     unsigned long long b) {
    asm("fma.rn.f32x2 %0, %1, %2, %0;" : "+l"(d) : "l"(a), "l"(b));
}
__device__ __forceinline__ unsigned long long pack2(float lo, float hi) {
    unsigned long long r;
    asm("mov.b64 %0, {%1,%2};" : "=l"(r) : "f"(lo), "f"(hi));
    return r;
}
__device__ __forceinline__ float2 unpack2(unsigned long long v) {
    float2 f;
    asm("mov.b64 {%0,%1}, %2;" : "=f"(f.x), "=f"(f.y) : "l"(v));
    return f;
}

// labels: loss init + dtype detect + convert + per-class lists (smem atomics)
__global__ void k_labels(const int* __restrict__ raw, int n,
                         float* out, int writeLoss) {
    __shared__ int odd_nz;
    __shared__ int scount[MAX_C];
    __shared__ int scursor[MAX_C];
    const int tid = threadIdx.x;
    if (tid == 0) {
        odd_nz = 0;
        if (writeLoss) out[0] = 0.0f;
    }
    if (tid < MAX_C) { scount[tid] = 0; scursor[tid] = 0; }
    __syncthreads();
    for (int i = tid; i < n / 2; i += 1024)
        if (raw[2 * i + 1] != 0) atomicOr(&odd_nz, 1);
    __syncthreads();
    const bool is32 = (odd_nz != 0);
    for (int i = tid; i < n; i += 1024) {
        int c = is32 ? raw[i] : raw[2 * i];
        g_labels[i] = c;
        atomicAdd(&scount[c], 1);
    }
    __syncthreads();
    if (tid < MAX_C) g_ccount[tid] = scount[tid];
    for (int i = tid; i < n; i += 1024) {
        int c = g_labels[i];
        int p = atomicAdd(&scursor[c], 1);
        g_clist[(size_t)c * MAX_N + p] = i;
    }
}

// ---- fused: v, blocked Cholesky, D/U, in-smem transpose, class solves -------
// (verbatim round-5 version; measured as part of the 139.8 us run)
__global__ __launch_bounds__(256, 2)
void k_fused(const float* __restrict__ sigma, const float* __restrict__ W,
             const float* __restrict__ F, const float* __restrict__ mu,
             int C, int K) {
    extern __shared__ float sh[];
    float* sA  = sh;                       // 128 * 132
    float* sW  = sA + A_DIM * PITCH;       // 128 * 33
    float* swl = sW + A_DIM * 33;          // 128
    float* sv  = swl + A_DIM;              // 128
    float* srd = sv + A_DIM;               // 128
    float* sdg = srd + A_DIM;              // 128
    float* sD  = sdg + A_DIM;              // 128
    float* sU  = sD + A_DIM;               // 128
    __shared__ float slogdet;

    const int s = blockIdx.x;
    const int cls = s / K;
    const int kk = s - cls * K;
    const int tid = threadIdx.x;
    const int wid = tid >> 5, lane = tid & 31;

    // ---- load Sigma (float4, coalesced), w_l; zero sD ----
    {
        const float4* src4 = reinterpret_cast<const float4*>(sigma + (size_t)s * A_DIM * A_DIM);
        for (int idx = tid; idx < A_DIM * 32; idx += 256) {
            int i = idx >> 5, f = idx & 31;
            *reinterpret_cast<float4*>(&sA[i * PITCH + 4 * f]) = src4[idx];
        }
        if (tid < A_DIM) { swl[tid] = W[cls * A_DIM + tid]; sD[tid] = 0.0f; }
    }
    __syncthreads();

    // ---- v = Sigma @ w_l (before factorization) ----
    if (tid < A_DIM) {
        float acc = 0.0f;
        #pragma unroll 8
        for (int b = 0; b < A_DIM; ++b) acc += sA[b * PITCH + tid] * swl[b];
        sv[tid] = acc;
    }
    __syncthreads();

    // ---- blocked Cholesky (NB = 32) ----
    for (int kb = 0; kb < A_DIM; kb += 32) {
        if (wid == 0) {
            float m[32];
            float* row = &sA[(kb + lane) * PITCH + kb];
            #pragma unroll
            for (int c = 0; c < 32; ++c) m[c] = row[c];
            #pragma unroll
            for (int j = 0; j < 32; ++j) {
                float dj = __shfl_sync(0xffffffffu, m[j], j);
                float l = m[j] * rsqrtf(dj);
                m[j] = l;
                #pragma unroll
                for (int p = j + 1; p < 32; ++p)
                    m[p] -= l * __shfl_sync(0xffffffffu, l, p);
            }
            #pragma unroll
            for (int c = 0; c < 32; ++c)
                if (c <= lane) row[c] = m[c];
            srd[kb + lane] = 1.0f / m[lane];
            sdg[kb + lane] = m[lane];
        }
        __syncthreads();

        const int R = A_DIM - kb - 32;
        if (R > 0) {
            if (tid < R) {
                const int row = kb + 32 + tid;
                float* pr = &sA[row * PITCH + kb];
                const float* pd = &sA[kb * PITCH + kb];
                float x[32];
                #pragma unroll
                for (int c = 0; c < 32; ++c) x[c] = pr[c];
                #pragma unroll
                for (int j = 0; j < 32; ++j) {
                    float a = x[j];
                    #pragma unroll
                    for (int p = 0; p < j; ++p) a -= x[p] * pd[j * PITCH + p];
                    x[j] = a * srd[kb + j];
                }
                #pragma unroll
                for (int c = 0; c < 32; ++c) pr[c] = x[c];
            }
            __syncthreads();

            const int nb = R >> 5;
            const int ntask = nb * (nb + 1);
            for (int task = wid; task < ntask; task += 8) {
                int b = 0, t = task;
                while (t >= 2 * b + 2) { t -= 2 * b + 2; ++b; }
                const int i  = kb + 32 + 32 * b + lane;
                const int j0 = kb + 32 + 16 * t;
                unsigned long long acc[16];
                #pragma unroll
                for (int q = 0; q < 16; ++q) acc[q] = 0ull;
                const float* pa = &sA[i * PITCH + kb];
                #pragma unroll
                for (int k = 0; k < 32; k += 4) {
                    ulonglong2 av = *reinterpret_cast<const ulonglong2*>(pa + k);
                    #pragma unroll
                    for (int q = 0; q < 16; ++q) {
                        ulonglong2 bv = *reinterpret_cast<const ulonglong2*>(
                            &sA[(j0 + q) * PITCH + kb + k]);
                        fma2(acc[q], av.x, bv.x);
                        fma2(acc[q], av.y, bv.y);
                    }
                }
                #pragma unroll
                for (int q = 0; q < 16; ++q) {
                    int col = j0 + q;
                    if (col <= i) {
                        float2 f = unpack2(acc[q]);
                        sA[i * PITCH + col] -= f.x + f.y;
                    }
                }
            }
            __syncthreads();
        }
    }

    // ---- zero upper triangle; logdet ----
    for (int idx = tid; idx < A_DIM * A_DIM; idx += 256) {
        int j = idx >> 7, i = idx & 127;
        if (i < j) sA[i * PITCH + j] = 0.0f;
    }
    if (tid < 32) {
        float v = logf(sdg[tid]) + logf(sdg[tid + 32]) +
                  logf(sdg[tid + 64]) + logf(sdg[tid + 96]);
        #pragma unroll
        for (int o = 16; o; o >>= 1) v += __shfl_xor_sync(0xffffffffu, v, o);
        if (tid == 0) slogdet = 2.0f * v;
    }

    // ---- D_c = ||L^T w_c||^2 (triangular, register-tiled), U_c = v . w_c ----
    for (int g = 0; g < 4; ++g) {
        __syncthreads();
        for (int idx = tid; idx < 32 * 32; idx += 256) {
            int cc = idx >> 5, f = idx & 31;
            int c = 32 * g + cc;
            float4 wv = (c < C) ? reinterpret_cast<const float4*>(W + (size_t)c * A_DIM)[f]
                                : make_float4(0.f, 0.f, 0.f, 0.f);
            sW[(4 * f + 0) * 33 + cc] = wv.x;
            sW[(4 * f + 1) * 33 + cc] = wv.y;
            sW[(4 * f + 2) * 33 + cc] = wv.z;
            sW[(4 * f + 3) * 33 + cc] = wv.w;
        }
        __syncthreads();

        const int t = (g & 1) ? (7 - wid) : wid;
        const int j0 = 16 * t;
        unsigned long long acc[8];
        #pragma unroll
        for (int q = 0; q < 8; ++q) acc[q] = 0ull;
        float u = 0.0f;
        const bool doU = (t == 0);

        for (int i = j0; i < A_DIM; ++i) {
            const float* Lr = &sA[i * PITCH + j0];
            float4 L0 = *reinterpret_cast<const float4*>(Lr);
            float4 L1 = *reinterpret_cast<const float4*>(Lr + 4);
            float4 L2 = *reinterpret_cast<const float4*>(Lr + 8);
            float4 L3 = *reinterpret_cast<const float4*>(Lr + 12);
            float wv = sW[i * 33 + lane];
            unsigned long long w2 = pack2(wv, wv);
            fma2(acc[0], pack2(L0.x, L0.y), w2);
            fma2(acc[1], pack2(L0.z, L0.w), w2);
            fma2(acc[2], pack2(L1.x, L1.y), w2);
            fma2(acc[3], pack2(L1.z, L1.w), w2);
            fma2(acc[4], pack2(L2.x, L2.y), w2);
            fma2(acc[5], pack2(L2.z, L2.w), w2);
            fma2(acc[6], pack2(L3.x, L3.y), w2);
            fma2(acc[7], pack2(L3.z, L3.w), w2);
            if (doU) u += sv[i] * wv;
        }
        unsigned long long d2 = 0ull;
        #pragma unroll
        for (int q = 0; q < 8; ++q) fma2(d2, acc[q], acc[q]);
        float2 dd = unpack2(d2);
        int c = 32 * g + lane;
        atomicAdd(&sD[c], dd.x + dd.y);
        if (doU) sU[c] = u;
    }
    __syncthreads();

    for (int c = tid; c < C; c += 256) {
        g_D[s * A_DIM + c] = sD[c];
        g_U[s * A_DIM + c] = sU[c];
    }

    // ---- in-place transpose: sA[j][i] = L[i][j] (i>j), zero the old lower ----
    for (int idx = tid; idx < A_DIM * A_DIM; idx += 256) {
        int i = idx >> 7, j = idx & 127;
        if (i > j) {
            float v = sA[i * PITCH + j];
            sA[j * PITCH + i] = v;
            sA[i * PITCH + j] = 0.0f;
        }
    }
    __syncthreads();

    // ---- class-grouped solves: score = dist + logdet, 4 samples per warp ----
    const int cnt = g_ccount[cls];
    const float logd = slogdet;
    const float4* F4 = reinterpret_cast<const float4*>(F);
    const float4 mv = reinterpret_cast<const float4*>(mu)[(size_t)s * 32 + lane];

    for (int m0 = wid * 4; m0 < cnt; m0 += 32) {
        int n[4];
        bool has[4];
        #pragma unroll
        for (int r = 0; r < 4; ++r) {
            has[r] = (m0 + r) < cnt;
            n[r] = g_clist[(size_t)cls * MAX_N + (has[r] ? (m0 + r) : m0)];
        }
        float d[4][4], dist[4];
        #pragma unroll
        for (int r = 0; r < 4; ++r) {
            float4 fv = F4[(size_t)n[r] * 32 + lane];
            d[r][0] = fv.x - mv.x; d[r][1] = fv.y - mv.y;
            d[r][2] = fv.z - mv.z; d[r][3] = fv.w - mv.w;
            dist[r] = 0.0f;
        }
        #pragma unroll 4
        for (int j = 0; j < A_DIM; ++j) {
            float4 col = *reinterpret_cast<const float4*>(&sA[j * PITCH + 4 * lane]);
            float rdj = srd[j];
            int owner = j >> 2, q = j & 3;
            #pragma unroll
            for (int r = 0; r < 4; ++r) {
                float dq = (q == 0) ? d[r][0] : (q == 1) ? d[r][1]
                         : (q == 2) ? d[r][2] : d[r][3];
                float z = __shfl_sync(0xffffffffu, dq, owner) * rdj;
                dist[r] += z * z;
                d[r][0] -= col.x * z;
                d[r][1] -= col.y * z;
                d[r][2] -= col.z * z;
                d[r][3] -= col.w * z;
            }
        }
        if (lane == 0) {
            #pragma unroll
            for (int r = 0; r < 4; ++r)
                if (has[r]) g_score[n[r] * 8 + kk] = dist[r] + logd;
        }
    }
}

// ---------------- fused y = F W^T + b, argmin, aug, log-softmax, loss --------
// Round-5 structure (NB=16, augv registers) widened to 512 threads (16 warps).
#define NB 16
#define YT 512
__global__ void k_yloss(const float* __restrict__ F, const float* __restrict__ W,
                        const float* __restrict__ bias, const float* __restrict__ ratioPtr,
                        float* __restrict__ yout, float* __restrict__ lossout,
                        int N, int C, int K, int writeLoss) {
    extern __shared__ float sh[];
    float* sWT = sh;                       // [128][C]
    float* sF  = sWT + A_DIM * C;          // [NB][128]
    float* sY  = sF + NB * A_DIM;          // [NB][C]
    float* sB  = sY + NB * C;              // [C]
    const int tid = threadIdx.x;
    const int n0 = blockIdx.x * NB;

    for (int idx = tid; idx < C * A_DIM; idx += YT) {
        int c = idx >> 7, aa = idx & 127;
        sWT[aa * C + c] = W[idx];
    }
    for (int idx = tid; idx < NB * A_DIM; idx += YT) {
        int nl = idx >> 7;
        int n = n0 + nl;
        sF[idx] = (n < N) ? F[(size_t)n * A_DIM + (idx & 127)] : 0.0f;
    }
    for (int c = tid; c < C; c += YT) sB[c] = bias[c];
    __syncthreads();

    const int warp = tid >> 5, lane = tid & 31;
    const int nwarp = YT / 32;             // 16
    const int nchunk = (C + 31) >> 5;

    for (int task = warp; task < NB * nchunk; task += nwarp) {
        int nl = task / nchunk;
        int c = (task - nl * nchunk) * 32 + lane;
        int n = n0 + nl;
        if (c < C && n < N) {
            float acc = sB[c];
            const float* f = sF + nl * A_DIM;
            #pragma unroll
            for (int aa = 0; aa < A_DIM; aa += 4) {
                float4 fv = *reinterpret_cast<const float4*>(f + aa);
                acc += fv.x * sWT[aa * C + c];
                acc += fv.y * sWT[(aa + 1) * C + c];
                acc += fv.z * sWT[(aa + 2) * C + c];
                acc += fv.w * sWT[(aa + 3) * C + c];
            }
            sY[nl * C + c] = acc;
            yout[(size_t)n * C + c] = acc;
        }
    }
    __syncthreads();

    const float hr = 0.5f * ratioPtr[0];
    for (int nl = warp; nl < NB; nl += nwarp) {
        int n = n0 + nl;
        if (n >= N) continue;
        int l = g_labels[n];
        const float* sc = g_score + n * 8;
        int k = 0;
        float best = sc[0];
        for (int kkk = 1; kkk < K; ++kkk) {
            float v = sc[kkk];
            if (v < best) { best = v; k = kkk; }
        }
        int s = l * K + k;
        const float* Dp = g_D + s * A_DIM;
        const float* Up = g_U + s * A_DIM;
        float ul = Up[l];
        float mymax = -INFINITY;
        float augv[8];
        for (int m = 0; m < nchunk; ++m) {
            int c = lane + 32 * m;
            float v = -INFINITY;
            if (c < C) v = sY[nl * C + c] + hr * (Dp[c] - 2.0f * Up[c] + ul);
            augv[m] = v;
            mymax = fmaxf(mymax, v);
        }
        #pragma unroll
        for (int o = 16; o; o >>= 1)
            mymax = fmaxf(mymax, __shfl_xor_sync(0xffffffffu, mymax, o));
        float sum = 0.0f;
        for (int m = 0; m < nchunk; ++m) {
            int c = lane + 32 * m;
            if (c < C) sum += expf(augv[m] - mymax);
        }
        #pragma unroll
        for (int o = 16; o; o >>= 1) sum += __shfl_xor_sync(0xffffffffu, sum, o);
        if (lane == 0 && writeLoss) {
            float lse = mymax + logf(sum);
            float aug_l = sY[nl * C + l] + hr * (Dp[l] - Up[l]);
            atomicAdd(lossout, (lse - aug_l) / (float)N);
        }
    }
}

// ---------------- launch -----------------------------------------------------
extern "C" void kernel_launch(void* const* d_in, const int* in_sizes, int n_in,
                              void* d_out, int out_size) {
    const float* F     = (const float*)d_in[0];
    const float* W     = (const float*)d_in[1];
    const float* bias  = (const float*)d_in[2];
    const float* mu    = (const float*)d_in[4];
    const float* sigma = (const float*)d_in[5];
    const int*   lraw  = (const int*)d_in[6];
    const float* ratio = (const float*)d_in[7];

    const int C = in_sizes[2];
    const int K = in_sizes[3] / C;
    const int Ad = in_sizes[1] / C;
    const int N = in_sizes[0] / Ad;
    const int S = C * K;

    float* out = (float*)d_out;
    const int yoff = out_size - N * C;
    const int writeLoss = (yoff >= 1) ? 1 : 0;
    float* yout = out + (yoff > 0 ? yoff : 0);

    const int smem_fused = (A_DIM * PITCH + A_DIM * 33 + 6 * A_DIM) * 4;   // 87552
    const int smem_yl    = (A_DIM * C + NB * A_DIM + NB * C + C) * 4;      // 66192

    cudaFuncSetAttribute(k_fused, cudaFuncAttributeMaxDynamicSharedMemorySize, smem_fused);
    cudaFuncSetAttribute(k_yloss, cudaFuncAttributeMaxDynamicSharedMemorySize, smem_yl);

    k_labels<<<1, 1024>>>(lraw, N, out, writeLoss);
    k_fused<<<S, 256, smem_fused>>>(sigma, W, F, mu, C, K);
    k_yloss<<<(N + NB - 1) / NB, YT, smem_yl>>>(F, W, bias, ratio, yout, out,
                                                N, C, K, writeLoss);
}

// round 9
// speedup vs baseline: 1.2155x; 1.0014x over previous
#include <cuda_runtime.h>
#include <math.h>

// ISDALoss_EM on GB300 — round 8: k_fused reverted verbatim to the measured-139.8
// round-5 version; k_labels from round 7 (smem atomics); k_yloss widened to 512 thr.
#define A_DIM 128
#define PITCH 132
#define MAX_S 512
#define MAX_N 4096
#define MAX_C 128

__device__ float g_D[MAX_S * A_DIM];
__device__ float g_U[MAX_S * A_DIM];
__device__ float g_score[MAX_N * 8];
__device__ int   g_labels[MAX_N];
__device__ int   g_ccount[MAX_C];
__device__ int   g_clist[(size_t)MAX_C * MAX_N];

__device__ __forceinline__ void fma2(unsigned long long& d, unsigned long long a,
                                     unsigned long long b) {
    asm("fma.rn.f32x2 %0, %1, %2, %0;" : "+l"(d) : "l"(a), "l"(b));
}
__device__ __forceinline__ unsigned long long pack2(float lo, float hi) {
    unsigned long long r;
    asm("mov.b64 %0, {%1,%2};" : "=l"(r) : "f"(lo), "f"(hi));
    return r;
}
__device__ __forceinline__ float2 unpack2(unsigned long long v) {
    float2 f;
    asm("mov.b64 {%0,%1}, %2;" : "=f"(f.x), "=f"(f.y) : "l"(v));
    return f;
}

// labels: loss init + dtype detect + convert + per-class lists (smem atomics)
__global__ void k_labels(const int* __restrict__ raw, int n,
                         float* out, int writeLoss) {
    __shared__ int odd_nz;
    __shared__ int scount[MAX_C];
    __shared__ int scursor[MAX_C];
    const int tid = threadIdx.x;
    if (tid == 0) {
        odd_nz = 0;
        if (writeLoss) out[0] = 0.0f;
    }
    if (tid < MAX_C) { scount[tid] = 0; scursor[tid] = 0; }
    __syncthreads();
    for (int i = tid; i < n / 2; i += 1024)
        if (raw[2 * i + 1] != 0) atomicOr(&odd_nz, 1);
    __syncthreads();
    const bool is32 = (odd_nz != 0);
    for (int i = tid; i < n; i += 1024) {
        int c = is32 ? raw[i] : raw[2 * i];
        g_labels[i] = c;
        atomicAdd(&scount[c], 1);
    }
    __syncthreads();
    if (tid < MAX_C) g_ccount[tid] = scount[tid];
    for (int i = tid; i < n; i += 1024) {
        int c = g_labels[i];
        int p = atomicAdd(&scursor[c], 1);
        g_clist[(size_t)c * MAX_N + p] = i;
    }
}

// ---- fused: v, blocked Cholesky, D/U, in-smem transpose, class solves -------
// (verbatim round-5 version; measured as part of the 139.8 us run)
__global__ __launch_bounds__(256, 2)
void k_fused(const float* __restrict__ sigma, const float* __restrict__ W,
             const float* __restrict__ F, const float* __restrict__ mu,
             int C, int K) {
    extern __shared__ float sh[];
    float* sA  = sh;                       // 128 * 132
    float* sW  = sA + A_DIM * PITCH;       // 128 * 33
    float* swl = sW + A_DIM * 33;          // 128
    float* sv  = swl + A_DIM;              // 128
    float* srd = sv + A_DIM;               // 128
    float* sdg = srd + A_DIM;              // 128
    float* sD  = sdg + A_DIM;              // 128
    float* sU  = sD + A_DIM;               // 128
    __shared__ float slogdet;

    const int s = blockIdx.x;
    const int cls = s / K;
    const int kk = s - cls * K;
    const int tid = threadIdx.x;
    const int wid = tid >> 5, lane = tid & 31;

    // ---- load Sigma (float4, coalesced), w_l; zero sD ----
    {
        const float4* src4 = reinterpret_cast<const float4*>(sigma + (size_t)s * A_DIM * A_DIM);
        for (int idx = tid; idx < A_DIM * 32; idx += 256) {
            int i = idx >> 5, f = idx & 31;
            *reinterpret_cast<float4*>(&sA[i * PITCH + 4 * f]) = src4[idx];
        }
        if (tid < A_DIM) { swl[tid] = W[cls * A_DIM + tid]; sD[tid] = 0.0f; }
    }
    __syncthreads();

    // ---- v = Sigma @ w_l (before factorization) ----
    if (tid < A_DIM) {
        float acc = 0.0f;
        #pragma unroll 8
        for (int b = 0; b < A_DIM; ++b) acc += sA[b * PITCH + tid] * swl[b];
        sv[tid] = acc;
    }
    __syncthreads();

    // ---- blocked Cholesky (NB = 32) ----
    for (int kb = 0; kb < A_DIM; kb += 32) {
        if (wid == 0) {
            float m[32];
            float* row = &sA[(kb + lane) * PITCH + kb];
            #pragma unroll
            for (int c = 0; c < 32; ++c) m[c] = row[c];
            #pragma unroll
            for (int j = 0; j < 32; ++j) {
                float dj = __shfl_sync(0xffffffffu, m[j], j);
                float l = m[j] * rsqrtf(dj);
                m[j] = l;
                #pragma unroll
                for (int p = j + 1; p < 32; ++p)
                    m[p] -= l * __shfl_sync(0xffffffffu, l, p);
            }
            #pragma unroll
            for (int c = 0; c < 32; ++c)
                if (c <= lane) row[c] = m[c];
            srd[kb + lane] = 1.0f / m[lane];
            sdg[kb + lane] = m[lane];
        }
        __syncthreads();

        const int R = A_DIM - kb - 32;
        if (R > 0) {
            if (tid < R) {
                const int row = kb + 32 + tid;
                float* pr = &sA[row * PITCH + kb];
                const float* pd = &sA[kb * PITCH + kb];
                float x[32];
                #pragma unroll
                for (int c = 0; c < 32; ++c) x[c] = pr[c];
                #pragma unroll
                for (int j = 0; j < 32; ++j) {
                    float a = x[j];
                    #pragma unroll
                    for (int p = 0; p < j; ++p) a -= x[p] * pd[j * PITCH + p];
                    x[j] = a * srd[kb + j];
                }
                #pragma unroll
                for (int c = 0; c < 32; ++c) pr[c] = x[c];
            }
            __syncthreads();

            const int nb = R >> 5;
            const int ntask = nb * (nb + 1);
            for (int task = wid; task < ntask; task += 8) {
                int b = 0, t = task;
                while (t >= 2 * b + 2) { t -= 2 * b + 2; ++b; }
                const int i  = kb + 32 + 32 * b + lane;
                const int j0 = kb + 32 + 16 * t;
                unsigned long long acc[16];
                #pragma unroll
                for (int q = 0; q < 16; ++q) acc[q] = 0ull;
                const float* pa = &sA[i * PITCH + kb];
                #pragma unroll
                for (int k = 0; k < 32; k += 4) {
                    ulonglong2 av = *reinterpret_cast<const ulonglong2*>(pa + k);
                    #pragma unroll
                    for (int q = 0; q < 16; ++q) {
                        ulonglong2 bv = *reinterpret_cast<const ulonglong2*>(
                            &sA[(j0 + q) * PITCH + kb + k]);
                        fma2(acc[q], av.x, bv.x);
                        fma2(acc[q], av.y, bv.y);
                    }
                }
                #pragma unroll
                for (int q = 0; q < 16; ++q) {
                    int col = j0 + q;
                    if (col <= i) {
                        float2 f = unpack2(acc[q]);
                        sA[i * PITCH + col] -= f.x + f.y;
                    }
                }
            }
            __syncthreads();
        }
    }

    // ---- zero upper triangle; logdet ----
    for (int idx = tid; idx < A_DIM * A_DIM; idx += 256) {
        int j = idx >> 7, i = idx & 127;
        if (i < j) sA[i * PITCH + j] = 0.0f;
    }
    if (tid < 32) {
        float v = logf(sdg[tid]) + logf(sdg[tid + 32]) +
                  logf(sdg[tid + 64]) + logf(sdg[tid + 96]);
        #pragma unroll
        for (int o = 16; o; o >>= 1) v += __shfl_xor_sync(0xffffffffu, v, o);
        if (tid == 0) slogdet = 2.0f * v;
    }

    // ---- D_c = ||L^T w_c||^2 (triangular, register-tiled), U_c = v . w_c ----
    for (int g = 0; g < 4; ++g) {
        __syncthreads();
        for (int idx = tid; idx < 32 * 32; idx += 256) {
            int cc = idx >> 5, f = idx & 31;
            int c = 32 * g + cc;
            float4 wv = (c < C) ? reinterpret_cast<const float4*>(W + (size_t)c * A_DIM)[f]
                                : make_float4(0.f, 0.f, 0.f, 0.f);
            sW[(4 * f + 0) * 33 + cc] = wv.x;
            sW[(4 * f + 1) * 33 + cc] = wv.y;
            sW[(4 * f + 2) * 33 + cc] = wv.z;
            sW[(4 * f + 3) * 33 + cc] = wv.w;
        }
        __syncthreads();

        const int t = (g & 1) ? (7 - wid) : wid;
        const int j0 = 16 * t;
        unsigned long long acc[8];
        #pragma unroll
        for (int q = 0; q < 8; ++q) acc[q] = 0ull;
        float u = 0.0f;
        const bool doU = (t == 0);

        for (int i = j0; i < A_DIM; ++i) {
            const float* Lr = &sA[i * PITCH + j0];
            float4 L0 = *reinterpret_cast<const float4*>(Lr);
            float4 L1 = *reinterpret_cast<const float4*>(Lr + 4);
            float4 L2 = *reinterpret_cast<const float4*>(Lr + 8);
            float4 L3 = *reinterpret_cast<const float4*>(Lr + 12);
            float wv = sW[i * 33 + lane];
            unsigned long long w2 = pack2(wv, wv);
            fma2(acc[0], pack2(L0.x, L0.y), w2);
            fma2(acc[1], pack2(L0.z, L0.w), w2);
            fma2(acc[2], pack2(L1.x, L1.y), w2);
            fma2(acc[3], pack2(L1.z, L1.w), w2);
            fma2(acc[4], pack2(L2.x, L2.y), w2);
            fma2(acc[5], pack2(L2.z, L2.w), w2);
            fma2(acc[6], pack2(L3.x, L3.y), w2);
            fma2(acc[7], pack2(L3.z, L3.w), w2);
            if (doU) u += sv[i] * wv;
        }
        unsigned long long d2 = 0ull;
        #pragma unroll
        for (int q = 0; q < 8; ++q) fma2(d2, acc[q], acc[q]);
        float2 dd = unpack2(d2);
        int c = 32 * g + lane;
        atomicAdd(&sD[c], dd.x + dd.y);
        if (doU) sU[c] = u;
    }
    __syncthreads();

    for (int c = tid; c < C; c += 256) {
        g_D[s * A_DIM + c] = sD[c];
        g_U[s * A_DIM + c] = sU[c];
    }

    // ---- in-place transpose: sA[j][i] = L[i][j] (i>j), zero the old lower ----
    for (int idx = tid; idx < A_DIM * A_DIM; idx += 256) {
        int i = idx >> 7, j = idx & 127;
        if (i > j) {
            float v = sA[i * PITCH + j];
            sA[j * PITCH + i] = v;
            sA[i * PITCH + j] = 0.0f;
        }
    }
    __syncthreads();

    // ---- class-grouped solves: score = dist + logdet, 4 samples per warp ----
    const int cnt = g_ccount[cls];
    const float logd = slogdet;
    const float4* F4 = reinterpret_cast<const float4*>(F);
    const float4 mv = reinterpret_cast<const float4*>(mu)[(size_t)s * 32 + lane];

    for (int m0 = wid * 4; m0 < cnt; m0 += 32) {
        int n[4];
        bool has[4];
        #pragma unroll
        for (int r = 0; r < 4; ++r) {
            has[r] = (m0 + r) < cnt;
            n[r] = g_clist[(size_t)cls * MAX_N + (has[r] ? (m0 + r) : m0)];
        }
        float d[4][4], dist[4];
        #pragma unroll
        for (int r = 0; r < 4; ++r) {
            float4 fv = F4[(size_t)n[r] * 32 + lane];
            d[r][0] = fv.x - mv.x; d[r][1] = fv.y - mv.y;
            d[r][2] = fv.z - mv.z; d[r][3] = fv.w - mv.w;
            dist[r] = 0.0f;
        }
        #pragma unroll 4
        for (int j = 0; j < A_DIM; ++j) {
            float4 col = *reinterpret_cast<const float4*>(&sA[j * PITCH + 4 * lane]);
            float rdj = srd[j];
            int owner = j >> 2, q = j & 3;
            #pragma unroll
            for (int r = 0; r < 4; ++r) {
                float dq = (q == 0) ? d[r][0] : (q == 1) ? d[r][1]
                         : (q == 2) ? d[r][2] : d[r][3];
                float z = __shfl_sync(0xffffffffu, dq, owner) * rdj;
                dist[r] += z * z;
                d[r][0] -= col.x * z;
                d[r][1] -= col.y * z;
                d[r][2] -= col.z * z;
                d[r][3] -= col.w * z;
            }
        }
        if (lane == 0) {
            #pragma unroll
            for (int r = 0; r < 4; ++r)
                if (has[r]) g_score[n[r] * 8 + kk] = dist[r] + logd;
        }
    }
}

// ---------------- fused y = F W^T + b, argmin, aug, log-softmax, loss --------
// Round-5 structure (NB=16, augv registers) widened to 512 threads (16 warps).
#define NB 16
#define YT 512
__global__ void k_yloss(const float* __restrict__ F, const float* __restrict__ W,
                        const float* __restrict__ bias, const float* __restrict__ ratioPtr,
                        float* __restrict__ yout, float* __restrict__ lossout,
                        int N, int C, int K, int writeLoss) {
    extern __shared__ float sh[];
    float* sWT = sh;                       // [128][C]
    float* sF  = sWT + A_DIM * C;          // [NB][128]
    float* sY  = sF + NB * A_DIM;          // [NB][C]
    float* sB  = sY + NB * C;              // [C]
    const int tid = threadIdx.x;
    const int n0 = blockIdx.x * NB;

    for (int idx = tid; idx < C * A_DIM; idx += YT) {
        int c = idx >> 7, aa = idx & 127;
        sWT[aa * C + c] = W[idx];
    }
    for (int idx = tid; idx < NB * A_DIM; idx += YT) {
        int nl = idx >> 7;
        int n = n0 + nl;
        sF[idx] = (n < N) ? F[(size_t)n * A_DIM + (idx & 127)] : 0.0f;
    }
    for (int c = tid; c < C; c += YT) sB[c] = bias[c];
    __syncthreads();

    const int warp = tid >> 5, lane = tid & 31;
    const int nwarp = YT / 32;             // 16
    const int nchunk = (C + 31) >> 5;

    for (int task = warp; task < NB * nchunk; task += nwarp) {
        int nl = task / nchunk;
        int c = (task - nl * nchunk) * 32 + lane;
        int n = n0 + nl;
        if (c < C && n < N) {
            float acc = sB[c];
            const float* f = sF + nl * A_DIM;
            #pragma unroll
            for (int aa = 0; aa < A_DIM; aa += 4) {
                float4 fv = *reinterpret_cast<const float4*>(f + aa);
                acc += fv.x * sWT[aa * C + c];
                acc += fv.y * sWT[(aa + 1) * C + c];
                acc += fv.z * sWT[(aa + 2) * C + c];
                acc += fv.w * sWT[(aa + 3) * C + c];
            }
            sY[nl * C + c] = acc;
            yout[(size_t)n * C + c] = acc;
        }
    }
    __syncthreads();

    const float hr = 0.5f * ratioPtr[0];
    for (int nl = warp; nl < NB; nl += nwarp) {
        int n = n0 + nl;
        if (n >= N) continue;
        int l = g_labels[n];
        const float* sc = g_score + n * 8;
        int k = 0;
        float best = sc[0];
        for (int kkk = 1; kkk < K; ++kkk) {
            float v = sc[kkk];
            if (v < best) { best = v; k = kkk; }
        }
        int s = l * K + k;
        const float* Dp = g_D + s * A_DIM;
        const float* Up = g_U + s * A_DIM;
        float ul = Up[l];
        float mymax = -INFINITY;
        float augv[8];
        for (int m = 0; m < nchunk; ++m) {
            int c = lane + 32 * m;
            float v = -INFINITY;
            if (c < C) v = sY[nl * C + c] + hr * (Dp[c] - 2.0f * Up[c] + ul);
            augv[m] = v;
            mymax = fmaxf(mymax, v);
        }
        #pragma unroll
        for (int o = 16; o; o >>= 1)
            mymax = fmaxf(mymax, __shfl_xor_sync(0xffffffffu, mymax, o));
        float sum = 0.0f;
        for (int m = 0; m < nchunk; ++m) {
            int c = lane + 32 * m;
            if (c < C) sum += expf(augv[m] - mymax);
        }
        #pragma unroll
        for (int o = 16; o; o >>= 1) sum += __shfl_xor_sync(0xffffffffu, sum, o);
        if (lane == 0 && writeLoss) {
            float lse = mymax + logf(sum);
            float aug_l = sY[nl * C + l] + hr * (Dp[l] - Up[l]);
            atomicAdd(lossout, (lse - aug_l) / (float)N);
        }
    }
}

// ---------------- launch -----------------------------------------------------
extern "C" void kernel_launch(void* const* d_in, const int* in_sizes, int n_in,
                              void* d_out, int out_size) {
    const float* F     = (const float*)d_in[0];
    const float* W     = (const float*)d_in[1];
    const float* bias  = (const float*)d_in[2];
    const float* mu    = (const float*)d_in[4];
    const float* sigma = (const float*)d_in[5];
    const int*   lraw  = (const int*)d_in[6];
    const float* ratio = (const float*)d_in[7];

    const int C = in_sizes[2];
    const int K = in_sizes[3] / C;
    const int Ad = in_sizes[1] / C;
    const int N = in_sizes[0] / Ad;
    const int S = C * K;

    float* out = (float*)d_out;
    const int yoff = out_size - N * C;
    const int writeLoss = (yoff >= 1) ? 1 : 0;
    float* yout = out + (yoff > 0 ? yoff : 0);

    const int smem_fused = (A_DIM * PITCH + A_DIM * 33 + 6 * A_DIM) * 4;   // 87552
    const int smem_yl    = (A_DIM * C + NB * A_DIM + NB * C + C) * 4;      // 66192

    cudaFuncSetAttribute(k_fused, cudaFuncAttributeMaxDynamicSharedMemorySize, smem_fused);
    cudaFuncSetAttribute(k_yloss, cudaFuncAttributeMaxDynamicSharedMemorySize, smem_yl);

    k_labels<<<1, 1024>>>(lraw, N, out, writeLoss);
    k_fused<<<S, 256, smem_fused>>>(sigma, W, F, mu, C, K);
    k_yloss<<<(N + NB - 1) / NB, YT, smem_yl>>>(F, W, bias, ratio, yout, out,
                                                N, C, K, writeLoss);
}

// round 10
// speedup vs baseline: 1.3538x; 1.1138x over previous
#include <cuda_runtime.h>
#include <math.h>

// ISDALoss_EM on GB300 — round 10: k_fused at 3 blocks/SM (smem diet: W staging
// replaced by pre-transposed g_WT reads; SYRK acc[16]->acc[8] for the reg cap).
#define A_DIM 128
#define PITCH 132
#define MAX_S 512
#define MAX_N 4096
#define MAX_C 128

__device__ float g_WT[A_DIM * A_DIM];     // WT[i][c] = W[c][i]; cols >= C stay 0
__device__ float g_D[MAX_S * A_DIM];
__device__ float g_U[MAX_S * A_DIM];
__device__ float g_score[MAX_N * 8];
__device__ int   g_labels[MAX_N];
__device__ int   g_ccount[MAX_C];
__device__ int   g_clist[(size_t)MAX_C * MAX_N];

__device__ __forceinline__ void fma2(unsigned long long& d, unsigned long long a,
                                     unsigned long long b) {
    asm("fma.rn.f32x2 %0, %1, %2, %0;" : "+l"(d) : "l"(a), "l"(b));
}
__device__ __forceinline__ unsigned long long pack2(float lo, float hi) {
    unsigned long long r;
    asm("mov.b64 %0, {%1,%2};" : "=l"(r) : "f"(lo), "f"(hi));
    return r;
}
__device__ __forceinline__ float2 unpack2(unsigned long long v) {
    float2 f;
    asm("mov.b64 {%0,%1}, %2;" : "=f"(f.x), "=f"(f.y) : "l"(v));
    return f;
}

// labels: loss init + dtype detect + convert + per-class lists + W transpose
__global__ void k_labels(const int* __restrict__ raw, const float* __restrict__ W,
                         int n, int C, float* out, int writeLoss) {
    __shared__ int odd_nz;
    __shared__ int scount[MAX_C];
    __shared__ int scursor[MAX_C];
    const int tid = threadIdx.x;
    if (tid == 0) {
        odd_nz = 0;
        if (writeLoss) out[0] = 0.0f;
    }
    if (tid < MAX_C) { scount[tid] = 0; scursor[tid] = 0; }
    __syncthreads();
    for (int i = tid; i < n / 2; i += 1024)
        if (raw[2 * i + 1] != 0) atomicOr(&odd_nz, 1);
    // transpose W while the flag settles (independent work)
    for (int idx = tid; idx < C * A_DIM; idx += 1024) {
        int c = idx >> 7, i = idx & 127;
        g_WT[i * A_DIM + c] = W[idx];
    }
    __syncthreads();
    const bool is32 = (odd_nz != 0);
    for (int i = tid; i < n; i += 1024) {
        int c = is32 ? raw[i] : raw[2 * i];
        g_labels[i] = c;
        atomicAdd(&scount[c], 1);
    }
    __syncthreads();
    if (tid < MAX_C) g_ccount[tid] = scount[tid];
    for (int i = tid; i < n; i += 1024) {
        int c = g_labels[i];
        int p = atomicAdd(&scursor[c], 1);
        g_clist[(size_t)c * MAX_N + p] = i;
    }
}

// ---- fused: v, blocked Cholesky, D/U, in-smem transpose, class solves -------
__global__ __launch_bounds__(256, 3)
void k_fused(const float* __restrict__ sigma, const float* __restrict__ W,
             const float* __restrict__ F, const float* __restrict__ mu,
             int C, int K) {
    extern __shared__ float sh[];
    float* sA  = sh;                       // 128 * 132
    float* swl = sA + A_DIM * PITCH;       // 128
    float* sv  = swl + A_DIM;              // 128
    float* srd = sv + A_DIM;               // 128
    float* sdg = srd + A_DIM;              // 128
    float* sD  = sdg + A_DIM;              // 128
    float* sU  = sD + A_DIM;               // 128
    __shared__ float slogdet;

    const int s = blockIdx.x;
    const int cls = s / K;
    const int kk = s - cls * K;
    const int tid = threadIdx.x;
    const int wid = tid >> 5, lane = tid & 31;

    // ---- load Sigma (float4, coalesced), w_l; zero sD ----
    {
        const float4* src4 = reinterpret_cast<const float4*>(sigma + (size_t)s * A_DIM * A_DIM);
        for (int idx = tid; idx < A_DIM * 32; idx += 256) {
            int i = idx >> 5, f = idx & 31;
            *reinterpret_cast<float4*>(&sA[i * PITCH + 4 * f]) = src4[idx];
        }
        if (tid < A_DIM) { swl[tid] = W[cls * A_DIM + tid]; sD[tid] = 0.0f; }
    }
    __syncthreads();

    // ---- v = Sigma @ w_l (before factorization) ----
    if (tid < A_DIM) {
        float acc = 0.0f;
        #pragma unroll 8
        for (int b = 0; b < A_DIM; ++b) acc += sA[b * PITCH + tid] * swl[b];
        sv[tid] = acc;
    }
    __syncthreads();

    // ---- blocked Cholesky (NB = 32) ----
    for (int kb = 0; kb < A_DIM; kb += 32) {
        if (wid == 0) {
            float m[32];
            float* row = &sA[(kb + lane) * PITCH + kb];
            #pragma unroll
            for (int c = 0; c < 32; ++c) m[c] = row[c];
            #pragma unroll
            for (int j = 0; j < 32; ++j) {
                float dj = __shfl_sync(0xffffffffu, m[j], j);
                float l = m[j] * rsqrtf(dj);
                m[j] = l;
                #pragma unroll
                for (int p = j + 1; p < 32; ++p)
                    m[p] -= l * __shfl_sync(0xffffffffu, l, p);
            }
            #pragma unroll
            for (int c = 0; c < 32; ++c)
                if (c <= lane) row[c] = m[c];
            srd[kb + lane] = 1.0f / m[lane];
            sdg[kb + lane] = m[lane];
        }
        __syncthreads();

        const int R = A_DIM - kb - 32;
        if (R > 0) {
            if (tid < R) {
                const int row = kb + 32 + tid;
                float* pr = &sA[row * PITCH + kb];
                const float* pd = &sA[kb * PITCH + kb];
                float x[32];
                #pragma unroll
                for (int c = 0; c < 32; ++c) x[c] = pr[c];
                #pragma unroll
                for (int j = 0; j < 32; ++j) {
                    float a = x[j];
                    #pragma unroll
                    for (int p = 0; p < j; ++p) a -= x[p] * pd[j * PITCH + p];
                    x[j] = a * srd[kb + j];
                }
                #pragma unroll
                for (int c = 0; c < 32; ++c) pr[c] = x[c];
            }
            __syncthreads();

            // SYRK: A22 -= L21 L21^T (lower), 8-col strips (acc[8] = 16 regs)
            const int nb = R >> 5;
            const int ntask = 2 * nb * (nb + 1);    // sum_b 4(b+1)
            for (int task = wid; task < ntask; task += 8) {
                int b = 0, t = task;
                while (t >= 4 * (b + 1)) { t -= 4 * (b + 1); ++b; }
                const int i  = kb + 32 + 32 * b + lane;
                const int j0 = kb + 32 + 8 * t;
                unsigned long long acc[8];
                #pragma unroll
                for (int q = 0; q < 8; ++q) acc[q] = 0ull;
                const float* pa = &sA[i * PITCH + kb];
                #pragma unroll
                for (int k = 0; k < 32; k += 4) {
                    ulonglong2 av = *reinterpret_cast<const ulonglong2*>(pa + k);
                    #pragma unroll
                    for (int q = 0; q < 8; ++q) {
                        ulonglong2 bv = *reinterpret_cast<const ulonglong2*>(
                            &sA[(j0 + q) * PITCH + kb + k]);
                        fma2(acc[q], av.x, bv.x);
                        fma2(acc[q], av.y, bv.y);
                    }
                }
                #pragma unroll
                for (int q = 0; q < 8; ++q) {
                    int col = j0 + q;
                    if (col <= i) {
                        float2 f = unpack2(acc[q]);
                        sA[i * PITCH + col] -= f.x + f.y;
                    }
                }
            }
            __syncthreads();
        }
    }

    // ---- zero upper triangle; logdet ----
    for (int idx = tid; idx < A_DIM * A_DIM; idx += 256) {
        int j = idx >> 7, i = idx & 127;
        if (i < j) sA[i * PITCH + j] = 0.0f;
    }
    if (tid < 32) {
        float v = logf(sdg[tid]) + logf(sdg[tid + 32]) +
                  logf(sdg[tid + 64]) + logf(sdg[tid + 96]);
        #pragma unroll
        for (int o = 16; o; o >>= 1) v += __shfl_xor_sync(0xffffffffu, v, o);
        if (tid == 0) slogdet = 2.0f * v;
    }
    __syncthreads();

    // ---- D_c = ||L^T w_c||^2 (register-tiled), U_c = v . w_c;
    //      w read straight from pre-transposed g_WT (L1/L2-hot) ----
    for (int g = 0; g < 4; ++g) {
        const int t = (g & 1) ? (7 - wid) : wid;   // balance across groups
        const int j0 = 16 * t;
        const int c = 32 * g + lane;
        unsigned long long acc[8];
        #pragma unroll
        for (int q = 0; q < 8; ++q) acc[q] = 0ull;
        float u = 0.0f;
        const bool doU = (t == 0);
        const float* wcol = g_WT + c;

        for (int i = j0; i < A_DIM; ++i) {
            const float* Lr = &sA[i * PITCH + j0];
            float4 L0 = *reinterpret_cast<const float4*>(Lr);
            float4 L1 = *reinterpret_cast<const float4*>(Lr + 4);
            float4 L2 = *reinterpret_cast<const float4*>(Lr + 8);
            float4 L3 = *reinterpret_cast<const float4*>(Lr + 12);
            float wv = wcol[i * A_DIM];            // coalesced 128B per warp
            unsigned long long w2 = pack2(wv, wv);
            fma2(acc[0], pack2(L0.x, L0.y), w2);
            fma2(acc[1], pack2(L0.z, L0.w), w2);
            fma2(acc[2], pack2(L1.x, L1.y), w2);
            fma2(acc[3], pack2(L1.z, L1.w), w2);
            fma2(acc[4], pack2(L2.x, L2.y), w2);
            fma2(acc[5], pack2(L2.z, L2.w), w2);
            fma2(acc[6], pack2(L3.x, L3.y), w2);
            fma2(acc[7], pack2(L3.z, L3.w), w2);
            if (doU) u += sv[i] * wv;
        }
        unsigned long long d2 = 0ull;
        #pragma unroll
        for (int q = 0; q < 8; ++q) fma2(d2, acc[q], acc[q]);
        float2 dd = unpack2(d2);
        atomicAdd(&sD[c], dd.x + dd.y);
        if (doU) sU[c] = u;
    }
    __syncthreads();

    for (int c = tid; c < C; c += 256) {
        g_D[s * A_DIM + c] = sD[c];
        g_U[s * A_DIM + c] = sU[c];
    }

    // ---- in-place transpose: sA[j][i] = L[i][j] (i>j), zero the old lower ----
    for (int idx = tid; idx < A_DIM * A_DIM; idx += 256) {
        int i = idx >> 7, j = idx & 127;
        if (i > j) {
            float v = sA[i * PITCH + j];
            sA[j * PITCH + i] = v;
            sA[i * PITCH + j] = 0.0f;
        }
    }
    __syncthreads();

    // ---- class-grouped solves: score = dist + logdet, 4 samples per warp ----
    const int cnt = g_ccount[cls];
    const float logd = slogdet;
    const float4* F4 = reinterpret_cast<const float4*>(F);
    const float4 mv = reinterpret_cast<const float4*>(mu)[(size_t)s * 32 + lane];

    for (int m0 = wid * 4; m0 < cnt; m0 += 32) {
        int n[4];
        bool has[4];
        #pragma unroll
        for (int r = 0; r < 4; ++r) {
            has[r] = (m0 + r) < cnt;
            n[r] = g_clist[(size_t)cls * MAX_N + (has[r] ? (m0 + r) : m0)];
        }
        float d[4][4], dist[4];
        #pragma unroll
        for (int r = 0; r < 4; ++r) {
            float4 fv = F4[(size_t)n[r] * 32 + lane];
            d[r][0] = fv.x - mv.x; d[r][1] = fv.y - mv.y;
            d[r][2] = fv.z - mv.z; d[r][3] = fv.w - mv.w;
            dist[r] = 0.0f;
        }
        #pragma unroll 4
        for (int j = 0; j < A_DIM; ++j) {
            float4 col = *reinterpret_cast<const float4*>(&sA[j * PITCH + 4 * lane]);
            float rdj = srd[j];
            int owner = j >> 2, q = j & 3;
            #pragma unroll
            for (int r = 0; r < 4; ++r) {
                float dq = (q == 0) ? d[r][0] : (q == 1) ? d[r][1]
                         : (q == 2) ? d[r][2] : d[r][3];
                float z = __shfl_sync(0xffffffffu, dq, owner) * rdj;
                dist[r] += z * z;
                d[r][0] -= col.x * z;
                d[r][1] -= col.y * z;
                d[r][2] -= col.z * z;
                d[r][3] -= col.w * z;
            }
        }
        if (lane == 0) {
            #pragma unroll
            for (int r = 0; r < 4; ++r)
                if (has[r]) g_score[n[r] * 8 + kk] = dist[r] + logd;
        }
    }
}

// ---------------- fused y = F W^T + b, argmin, aug, log-softmax, loss --------
#define NB 16
#define YT 512
__global__ void k_yloss(const float* __restrict__ F, const float* __restrict__ W,
                        const float* __restrict__ bias, const float* __restrict__ ratioPtr,
                        float* __restrict__ yout, float* __restrict__ lossout,
                        int N, int C, int K, int writeLoss) {
    extern __shared__ float sh[];
    float* sWT = sh;                       // [128][C]
    float* sF  = sWT + A_DIM * C;          // [NB][128]
    float* sY  = sF + NB * A_DIM;          // [NB][C]
    float* sB  = sY + NB * C;              // [C]
    const int tid = threadIdx.x;
    const int n0 = blockIdx.x * NB;

    for (int idx = tid; idx < C * A_DIM; idx += YT) {
        int c = idx >> 7, aa = idx & 127;
        sWT[aa * C + c] = W[idx];
    }
    for (int idx = tid; idx < NB * A_DIM; idx += YT) {
        int nl = idx >> 7;
        int n = n0 + nl;
        sF[idx] = (n < N) ? F[(size_t)n * A_DIM + (idx & 127)] : 0.0f;
    }
    for (int c = tid; c < C; c += YT) sB[c] = bias[c];
    __syncthreads();

    const int warp = tid >> 5, lane = tid & 31;
    const int nwarp = YT / 32;
    const int nchunk = (C + 31) >> 5;

    for (int task = warp; task < NB * nchunk; task += nwarp) {
        int nl = task / nchunk;
        int c = (task - nl * nchunk) * 32 + lane;
        int n = n0 + nl;
        if (c < C && n < N) {
            float acc = sB[c];
            const float* f = sF + nl * A_DIM;
            #pragma unroll
            for (int aa = 0; aa < A_DIM; aa += 4) {
                float4 fv = *reinterpret_cast<const float4*>(f + aa);
                acc += fv.x * sWT[aa * C + c];
                acc += fv.y * sWT[(aa + 1) * C + c];
                acc += fv.z * sWT[(aa + 2) * C + c];
                acc += fv.w * sWT[(aa + 3) * C + c];
            }
            sY[nl * C + c] = acc;
            yout[(size_t)n * C + c] = acc;
        }
    }
    __syncthreads();

    const float hr = 0.5f * ratioPtr[0];
    for (int nl = warp; nl < NB; nl += nwarp) {
        int n = n0 + nl;
        if (n >= N) continue;
        int l = g_labels[n];
        const float* sc = g_score + n * 8;
        int k = 0;
        float best = sc[0];
        for (int kkk = 1; kkk < K; ++kkk) {
            float v = sc[kkk];
            if (v < best) { best = v; k = kkk; }
        }
        int s = l * K + k;
        const float* Dp = g_D + s * A_DIM;
        const float* Up = g_U + s * A_DIM;
        float ul = Up[l];
        float mymax = -INFINITY;
        float augv[8];
        for (int m = 0; m < nchunk; ++m) {
            int c = lane + 32 * m;
            float v = -INFINITY;
            if (c < C) v = sY[nl * C + c] + hr * (Dp[c] - 2.0f * Up[c] + ul);
            augv[m] = v;
            mymax = fmaxf(mymax, v);
        }
        #pragma unroll
        for (int o = 16; o; o >>= 1)
            mymax = fmaxf(mymax, __shfl_xor_sync(0xffffffffu, mymax, o));
        float sum = 0.0f;
        for (int m = 0; m < nchunk; ++m) {
            int c = lane + 32 * m;
            if (c < C) sum += expf(augv[m] - mymax);
        }
        #pragma unroll
        for (int o = 16; o; o >>= 1) sum += __shfl_xor_sync(0xffffffffu, sum, o);
        if (lane == 0 && writeLoss) {
            float lse = mymax + logf(sum);
            float aug_l = sY[nl * C + l] + hr * (Dp[l] - Up[l]);
            atomicAdd(lossout, (lse - aug_l) / (float)N);
        }
    }
}

// ---------------- launch -----------------------------------------------------
extern "C" void kernel_launch(void* const* d_in, const int* in_sizes, int n_in,
                              void* d_out, int out_size) {
    const float* F     = (const float*)d_in[0];
    const float* W     = (const float*)d_in[1];
    const float* bias  = (const float*)d_in[2];
    const float* mu    = (const float*)d_in[4];
    const float* sigma = (const float*)d_in[5];
    const int*   lraw  = (const int*)d_in[6];
    const float* ratio = (const float*)d_in[7];

    const int C = in_sizes[2];
    const int K = in_sizes[3] / C;
    const int Ad = in_sizes[1] / C;
    const int N = in_sizes[0] / Ad;
    const int S = C * K;

    float* out = (float*)d_out;
    const int yoff = out_size - N * C;
    const int writeLoss = (yoff >= 1) ? 1 : 0;
    float* yout = out + (yoff > 0 ? yoff : 0);

    const int smem_fused = (A_DIM * PITCH + 6 * A_DIM) * 4;                // 70656
    const int smem_yl    = (A_DIM * C + NB * A_DIM + NB * C + C) * 4;      // 66192

    cudaFuncSetAttribute(k_fused, cudaFuncAttributeMaxDynamicSharedMemorySize, smem_fused);
    cudaFuncSetAttribute(k_yloss, cudaFuncAttributeMaxDynamicSharedMemorySize, smem_yl);

    k_labels<<<1, 1024>>>(lraw, W, N, C, out, writeLoss);
    k_fused<<<S, 256, smem_fused>>>(sigma, W, F, mu, C, K);
    k_yloss<<<(N + NB - 1) / NB, YT, smem_yl>>>(F, W, bias, ratio, yout, out,
                                                N, C, K, writeLoss);
}

// round 11
// speedup vs baseline: 1.4440x; 1.0666x over previous
#include <cuda_runtime.h>
#include <math.h>

// ISDALoss_EM on GB300 — round 11: W-transpose in its own tiled kernel;
// k_labels back to round-9 form; skip dead-lower zeroing in k_fused.
#define A_DIM 128
#define PITCH 132
#define MAX_S 512
#define MAX_N 4096
#define MAX_C 128

__device__ float g_WT[A_DIM * A_DIM];     // WT[i][c] = W[c][i]; c >= C zeroed
__device__ float g_D[MAX_S * A_DIM];
__device__ float g_U[MAX_S * A_DIM];
__device__ float g_score[MAX_N * 8];
__device__ int   g_labels[MAX_N];
__device__ int   g_ccount[MAX_C];
__device__ int   g_clist[(size_t)MAX_C * MAX_N];

__device__ __forceinline__ void fma2(unsigned long long& d, unsigned long long a,
                                     unsigned long long b) {
    asm("fma.rn.f32x2 %0, %1, %2, %0;" : "+l"(d) : "l"(a), "l"(b));
}
__device__ __forceinline__ unsigned long long pack2(float lo, float hi) {
    unsigned long long r;
    asm("mov.b64 %0, {%1,%2};" : "=l"(r) : "f"(lo), "f"(hi));
    return r;
}
__device__ __forceinline__ float2 unpack2(unsigned long long v) {
    float2 f;
    asm("mov.b64 {%0,%1}, %2;" : "=f"(f.x), "=f"(f.y) : "l"(v));
    return f;
}

// ---- W transpose: 32x32 smem tiles, coalesced both directions --------------
__global__ void k_wt(const float* __restrict__ W, int C) {
    __shared__ float tile[32][33];
    const int ct0 = blockIdx.x * 32;       // c tile base
    const int it0 = blockIdx.y * 32;       // i tile base
    const int tid = threadIdx.x;           // 256 threads = 8 rows/pass
    const int tr = tid >> 5, tc = tid & 31;
    #pragma unroll
    for (int r = 0; r < 32; r += 8) {
        int c = ct0 + tr + r;
        tile[tr + r][tc] = (c < C) ? W[(size_t)c * A_DIM + it0 + tc] : 0.0f;
    }
    __syncthreads();
    #pragma unroll
    for (int r = 0; r < 32; r += 8) {
        int i = it0 + tr + r;
        g_WT[(size_t)i * A_DIM + ct0 + tc] = tile[tc][tr + r];
    }
}

// labels: loss init + dtype detect + convert + per-class lists (smem atomics)
__global__ void k_labels(const int* __restrict__ raw, int n,
                         float* out, int writeLoss) {
    __shared__ int odd_nz;
    __shared__ int scount[MAX_C];
    __shared__ int scursor[MAX_C];
    const int tid = threadIdx.x;
    if (tid == 0) {
        odd_nz = 0;
        if (writeLoss) out[0] = 0.0f;
    }
    if (tid < MAX_C) { scount[tid] = 0; scursor[tid] = 0; }
    __syncthreads();
    for (int i = tid; i < n / 2; i += 1024)
        if (raw[2 * i + 1] != 0) atomicOr(&odd_nz, 1);
    __syncthreads();
    const bool is32 = (odd_nz != 0);
    for (int i = tid; i < n; i += 1024) {
        int c = is32 ? raw[i] : raw[2 * i];
        g_labels[i] = c;
        atomicAdd(&scount[c], 1);
    }
    __syncthreads();
    if (tid < MAX_C) g_ccount[tid] = scount[tid];
    for (int i = tid; i < n; i += 1024) {
        int c = g_labels[i];
        int p = atomicAdd(&scursor[c], 1);
        g_clist[(size_t)c * MAX_N + p] = i;
    }
}

// ---- fused: v, blocked Cholesky, D/U, in-smem transpose, class solves -------
__global__ __launch_bounds__(256, 3)
void k_fused(const float* __restrict__ sigma, const float* __restrict__ W,
             const float* __restrict__ F, const float* __restrict__ mu,
             int C, int K) {
    extern __shared__ float sh[];
    float* sA  = sh;                       // 128 * 132
    float* swl = sA + A_DIM * PITCH;       // 128
    float* sv  = swl + A_DIM;              // 128
    float* srd = sv + A_DIM;               // 128
    float* sdg = srd + A_DIM;              // 128
    float* sD  = sdg + A_DIM;              // 128
    float* sU  = sD + A_DIM;               // 128
    __shared__ float slogdet;

    const int s = blockIdx.x;
    const int cls = s / K;
    const int kk = s - cls * K;
    const int tid = threadIdx.x;
    const int wid = tid >> 5, lane = tid & 31;

    // ---- load Sigma (float4, coalesced), w_l; zero sD ----
    {
        const float4* src4 = reinterpret_cast<const float4*>(sigma + (size_t)s * A_DIM * A_DIM);
        for (int idx = tid; idx < A_DIM * 32; idx += 256) {
            int i = idx >> 5, f = idx & 31;
            *reinterpret_cast<float4*>(&sA[i * PITCH + 4 * f]) = src4[idx];
        }
        if (tid < A_DIM) { swl[tid] = W[cls * A_DIM + tid]; sD[tid] = 0.0f; }
    }
    __syncthreads();

    // ---- v = Sigma @ w_l (before factorization) ----
    if (tid < A_DIM) {
        float acc = 0.0f;
        #pragma unroll 8
        for (int b = 0; b < A_DIM; ++b) acc += sA[b * PITCH + tid] * swl[b];
        sv[tid] = acc;
    }
    __syncthreads();

    // ---- blocked Cholesky (NB = 32) ----
    for (int kb = 0; kb < A_DIM; kb += 32) {
        if (wid == 0) {
            float m[32];
            float* row = &sA[(kb + lane) * PITCH + kb];
            #pragma unroll
            for (int c = 0; c < 32; ++c) m[c] = row[c];
            #pragma unroll
            for (int j = 0; j < 32; ++j) {
                float dj = __shfl_sync(0xffffffffu, m[j], j);
                float l = m[j] * rsqrtf(dj);
                m[j] = l;
                #pragma unroll
                for (int p = j + 1; p < 32; ++p)
                    m[p] -= l * __shfl_sync(0xffffffffu, l, p);
            }
            #pragma unroll
            for (int c = 0; c < 32; ++c)
                if (c <= lane) row[c] = m[c];
            srd[kb + lane] = 1.0f / m[lane];
            sdg[kb + lane] = m[lane];
        }
        __syncthreads();

        const int R = A_DIM - kb - 32;
        if (R > 0) {
            if (tid < R) {
                const int row = kb + 32 + tid;
                float* pr = &sA[row * PITCH + kb];
                const float* pd = &sA[kb * PITCH + kb];
                float x[32];
                #pragma unroll
                for (int c = 0; c < 32; ++c) x[c] = pr[c];
                #pragma unroll
                for (int j = 0; j < 32; ++j) {
                    float a = x[j];
                    #pragma unroll
                    for (int p = 0; p < j; ++p) a -= x[p] * pd[j * PITCH + p];
                    x[j] = a * srd[kb + j];
                }
                #pragma unroll
                for (int c = 0; c < 32; ++c) pr[c] = x[c];
            }
            __syncthreads();

            // SYRK: A22 -= L21 L21^T (lower), 8-col strips
            const int nb = R >> 5;
            const int ntask = 2 * nb * (nb + 1);
            for (int task = wid; task < ntask; task += 8) {
                int b = 0, t = task;
                while (t >= 4 * (b + 1)) { t -= 4 * (b + 1); ++b; }
                const int i  = kb + 32 + 32 * b + lane;
                const int j0 = kb + 32 + 8 * t;
                unsigned long long acc[8];
                #pragma unroll
                for (int q = 0; q < 8; ++q) acc[q] = 0ull;
                const float* pa = &sA[i * PITCH + kb];
                #pragma unroll
                for (int k = 0; k < 32; k += 4) {
                    ulonglong2 av = *reinterpret_cast<const ulonglong2*>(pa + k);
                    #pragma unroll
                    for (int q = 0; q < 8; ++q) {
                        ulonglong2 bv = *reinterpret_cast<const ulonglong2*>(
                            &sA[(j0 + q) * PITCH + kb + k]);
                        fma2(acc[q], av.x, bv.x);
                        fma2(acc[q], av.y, bv.y);
                    }
                }
                #pragma unroll
                for (int q = 0; q < 8; ++q) {
                    int col = j0 + q;
                    if (col <= i) {
                        float2 f = unpack2(acc[q]);
                        sA[i * PITCH + col] -= f.x + f.y;
                    }
                }
            }
            __syncthreads();
        }
    }

    // ---- zero upper triangle; logdet ----
    for (int idx = tid; idx < A_DIM * A_DIM; idx += 256) {
        int j = idx >> 7, i = idx & 127;
        if (i < j) sA[i * PITCH + j] = 0.0f;
    }
    if (tid < 32) {
        float v = logf(sdg[tid]) + logf(sdg[tid + 32]) +
                  logf(sdg[tid + 64]) + logf(sdg[tid + 96]);
        #pragma unroll
        for (int o = 16; o; o >>= 1) v += __shfl_xor_sync(0xffffffffu, v, o);
        if (tid == 0) slogdet = 2.0f * v;
    }
    __syncthreads();

    // ---- D_c = ||L^T w_c||^2 (register-tiled), U_c = v . w_c;
    //      w from pre-transposed g_WT (L1/L2-hot) ----
    for (int g = 0; g < 4; ++g) {
        const int t = (g & 1) ? (7 - wid) : wid;
        const int j0 = 16 * t;
        const int c = 32 * g + lane;
        unsigned long long acc[8];
        #pragma unroll
        for (int q = 0; q < 8; ++q) acc[q] = 0ull;
        float u = 0.0f;
        const bool doU = (t == 0);
        const float* wcol = g_WT + c;

        for (int i = j0; i < A_DIM; ++i) {
            const float* Lr = &sA[i * PITCH + j0];
            float4 L0 = *reinterpret_cast<const float4*>(Lr);
            float4 L1 = *reinterpret_cast<const float4*>(Lr + 4);
            float4 L2 = *reinterpret_cast<const float4*>(Lr + 8);
            float4 L3 = *reinterpret_cast<const float4*>(Lr + 12);
            float wv = wcol[i * A_DIM];
            unsigned long long w2 = pack2(wv, wv);
            fma2(acc[0], pack2(L0.x, L0.y), w2);
            fma2(acc[1], pack2(L0.z, L0.w), w2);
            fma2(acc[2], pack2(L1.x, L1.y), w2);
            fma2(acc[3], pack2(L1.z, L1.w), w2);
            fma2(acc[4], pack2(L2.x, L2.y), w2);
            fma2(acc[5], pack2(L2.z, L2.w), w2);
            fma2(acc[6], pack2(L3.x, L3.y), w2);
            fma2(acc[7], pack2(L3.z, L3.w), w2);
            if (doU) u += sv[i] * wv;
        }
        unsigned long long d2 = 0ull;
        #pragma unroll
        for (int q = 0; q < 8; ++q) fma2(d2, acc[q], acc[q]);
        float2 dd = unpack2(d2);
        atomicAdd(&sD[c], dd.x + dd.y);
        if (doU) sU[c] = u;
    }
    __syncthreads();

    for (int c = tid; c < C; c += 256) {
        g_D[s * A_DIM + c] = sD[c];
        g_U[s * A_DIM + c] = sU[c];
    }

    // ---- transpose lower -> upper. Stale lower entries are dead in the solve:
    //      any d[i] they corrupt was consumed at step i < j. ----
    for (int idx = tid; idx < A_DIM * A_DIM; idx += 256) {
        int i = idx >> 7, j = idx & 127;
        if (i > j) sA[j * PITCH + i] = sA[i * PITCH + j];
    }
    __syncthreads();

    // ---- class-grouped solves: score = dist + logdet, 4 samples per warp ----
    const int cnt = g_ccount[cls];
    const float logd = slogdet;
    const float4* F4 = reinterpret_cast<const float4*>(F);
    const float4 mv = reinterpret_cast<const float4*>(mu)[(size_t)s * 32 + lane];

    for (int m0 = wid * 4; m0 < cnt; m0 += 32) {
        int n[4];
        bool has[4];
        #pragma unroll
        for (int r = 0; r < 4; ++r) {
            has[r] = (m0 + r) < cnt;
            n[r] = g_clist[(size_t)cls * MAX_N + (has[r] ? (m0 + r) : m0)];
        }
        float d[4][4], dist[4];
        #pragma unroll
        for (int r = 0; r < 4; ++r) {
            float4 fv = F4[(size_t)n[r] * 32 + lane];
            d[r][0] = fv.x - mv.x; d[r][1] = fv.y - mv.y;
            d[r][2] = fv.z - mv.z; d[r][3] = fv.w - mv.w;
            dist[r] = 0.0f;
        }
        #pragma unroll 4
        for (int j = 0; j < A_DIM; ++j) {
            float4 col = *reinterpret_cast<const float4*>(&sA[j * PITCH + 4 * lane]);
            float rdj = srd[j];
            int owner = j >> 2, q = j & 3;
            #pragma unroll
            for (int r = 0; r < 4; ++r) {
                float dq = (q == 0) ? d[r][0] : (q == 1) ? d[r][1]
                         : (q == 2) ? d[r][2] : d[r][3];
                float z = __shfl_sync(0xffffffffu, dq, owner) * rdj;
                dist[r] += z * z;
                d[r][0] -= col.x * z;
                d[r][1] -= col.y * z;
                d[r][2] -= col.z * z;
                d[r][3] -= col.w * z;
            }
        }
        if (lane == 0) {
            #pragma unroll
            for (int r = 0; r < 4; ++r)
                if (has[r]) g_score[n[r] * 8 + kk] = dist[r] + logd;
        }
    }
}

// ---------------- fused y = F W^T + b, argmin, aug, log-softmax, loss --------
#define NB 16
#define YT 512
__global__ void k_yloss(const float* __restrict__ F, const float* __restrict__ W,
                        const float* __restrict__ bias, const float* __restrict__ ratioPtr,
                        float* __restrict__ yout, float* __restrict__ lossout,
                        int N, int C, int K, int writeLoss) {
    extern __shared__ float sh[];
    float* sWT = sh;                       // [128][C]
    float* sF  = sWT + A_DIM * C;          // [NB][128]
    float* sY  = sF + NB * A_DIM;          // [NB][C]
    float* sB  = sY + NB * C;              // [C]
    const int tid = threadIdx.x;
    const int n0 = blockIdx.x * NB;

    for (int idx = tid; idx < C * A_DIM; idx += YT) {
        int c = idx >> 7, aa = idx & 127;
        sWT[aa * C + c] = W[idx];
    }
    for (int idx = tid; idx < NB * A_DIM; idx += YT) {
        int nl = idx >> 7;
        int n = n0 + nl;
        sF[idx] = (n < N) ? F[(size_t)n * A_DIM + (idx & 127)] : 0.0f;
    }
    for (int c = tid; c < C; c += YT) sB[c] = bias[c];
    __syncthreads();

    const int warp = tid >> 5, lane = tid & 31;
    const int nwarp = YT / 32;
    const int nchunk = (C + 31) >> 5;

    for (int task = warp; task < NB * nchunk; task += nwarp) {
        int nl = task / nchunk;
        int c = (task - nl * nchunk) * 32 + lane;
        int n = n0 + nl;
        if (c < C && n < N) {
            float acc = sB[c];
            const float* f = sF + nl * A_DIM;
            #pragma unroll
            for (int aa = 0; aa < A_DIM; aa += 4) {
                float4 fv = *reinterpret_cast<const float4*>(f + aa);
                acc += fv.x * sWT[aa * C + c];
                acc += fv.y * sWT[(aa + 1) * C + c];
                acc += fv.z * sWT[(aa + 2) * C + c];
                acc += fv.w * sWT[(aa + 3) * C + c];
            }
            sY[nl * C + c] = acc;
            yout[(size_t)n * C + c] = acc;
        }
    }
    __syncthreads();

    const float hr = 0.5f * ratioPtr[0];
    for (int nl = warp; nl < NB; nl += nwarp) {
        int n = n0 + nl;
        if (n >= N) continue;
        int l = g_labels[n];
        const float* sc = g_score + n * 8;
        int k = 0;
        float best = sc[0];
        for (int kkk = 1; kkk < K; ++kkk) {
            float v = sc[kkk];
            if (v < best) { best = v; k = kkk; }
        }
        int s = l * K + k;
        const float* Dp = g_D + s * A_DIM;
        const float* Up = g_U + s * A_DIM;
        float ul = Up[l];
        float mymax = -INFINITY;
        float augv[8];
        for (int m = 0; m < nchunk; ++m) {
            int c = lane + 32 * m;
            float v = -INFINITY;
            if (c < C) v = sY[nl * C + c] + hr * (Dp[c] - 2.0f * Up[c] + ul);
            augv[m] = v;
            mymax = fmaxf(mymax, v);
        }
        #pragma unroll
        for (int o = 16; o; o >>= 1)
            mymax = fmaxf(mymax, __shfl_xor_sync(0xffffffffu, mymax, o));
        float sum = 0.0f;
        for (int m = 0; m < nchunk; ++m) {
            int c = lane + 32 * m;
            if (c < C) sum += expf(augv[m] - mymax);
        }
        #pragma unroll
        for (int o = 16; o; o >>= 1) sum += __shfl_xor_sync(0xffffffffu, sum, o);
        if (lane == 0 && writeLoss) {
            float lse = mymax + logf(sum);
            float aug_l = sY[nl * C + l] + hr * (Dp[l] - Up[l]);
            atomicAdd(lossout, (lse - aug_l) / (float)N);
        }
    }
}

// ---------------- launch -----------------------------------------------------
extern "C" void kernel_launch(void* const* d_in, const int* in_sizes, int n_in,
                              void* d_out, int out_size) {
    const float* F     = (const float*)d_in[0];
    const float* W     = (const float*)d_in[1];
    const float* bias  = (const float*)d_in[2];
    const float* mu    = (const float*)d_in[4];
    const float* sigma = (const float*)d_in[5];
    const int*   lraw  = (const int*)d_in[6];
    const float* ratio = (const float*)d_in[7];

    const int C = in_sizes[2];
    const int K = in_sizes[3] / C;
    const int Ad = in_sizes[1] / C;
    const int N = in_sizes[0] / Ad;
    const int S = C * K;

    float* out = (float*)d_out;
    const int yoff = out_size - N * C;
    const int writeLoss = (yoff >= 1) ? 1 : 0;
    float* yout = out + (yoff > 0 ? yoff : 0);

    const int smem_fused = (A_DIM * PITCH + 6 * A_DIM) * 4;                // 70656
    const int smem_yl    = (A_DIM * C + NB * A_DIM + NB * C + C) * 4;      // 66192

    cudaFuncSetAttribute(k_fused, cudaFuncAttributeMaxDynamicSharedMemorySize, smem_fused);
    cudaFuncSetAttribute(k_yloss, cudaFuncAttributeMaxDynamicSharedMemorySize, smem_yl);

    dim3 wtgrid(4, 4);
    k_wt<<<wtgrid, 256>>>(W, C);
    k_labels<<<1, 1024>>>(lraw, N, out, writeLoss);
    k_fused<<<S, 256, smem_fused>>>(sigma, W, F, mu, C, K);
    k_yloss<<<(N + NB - 1) / NB, YT, smem_yl>>>(F, W, bias, ratio, yout, out,
                                                N, C, K, writeLoss);
}

// round 12
// speedup vs baseline: 1.4497x; 1.0039x over previous
#include <cuda_runtime.h>
#include <math.h>

// ISDALoss_EM on GB300 — round 12: k_yloss de-spill (unroll-limited GEMM,
// in-place aug); k_labels gridded (redundant detect, distributed atomics);
// k_fused byte-identical to the measured-115.2 version.
#define A_DIM 128
#define PITCH 132
#define MAX_S 512
#define MAX_N 4096
#define MAX_C 128

__device__ float g_WT[A_DIM * A_DIM];     // WT[i][c] = W[c][i]; c >= C zeroed
__device__ float g_D[MAX_S * A_DIM];
__device__ float g_U[MAX_S * A_DIM];
__device__ float g_score[MAX_N * 8];
__device__ int   g_labels[MAX_N];
__device__ int   g_ccount[MAX_C];
__device__ int   g_clist[(size_t)MAX_C * MAX_N];

__device__ __forceinline__ void fma2(unsigned long long& d, unsigned long long a,
                                     unsigned long long b) {
    asm("fma.rn.f32x2 %0, %1, %2, %0;" : "+l"(d) : "l"(a), "l"(b));
}
__device__ __forceinline__ unsigned long long pack2(float lo, float hi) {
    unsigned long long r;
    asm("mov.b64 %0, {%1,%2};" : "=l"(r) : "f"(lo), "f"(hi));
    return r;
}
__device__ __forceinline__ float2 unpack2(unsigned long long v) {
    float2 f;
    asm("mov.b64 {%0,%1}, %2;" : "=f"(f.x), "=f"(f.y) : "l"(v));
    return f;
}

// ---- W transpose (coalesced both ways) + zero g_ccount for k_labels --------
__global__ void k_wt(const float* __restrict__ W, int C) {
    __shared__ float tile[32][33];
    if (blockIdx.x == 0 && blockIdx.y == 0 && threadIdx.x < MAX_C)
        g_ccount[threadIdx.x] = 0;
    const int ct0 = blockIdx.x * 32;
    const int it0 = blockIdx.y * 32;
    const int tid = threadIdx.x;
    const int tr = tid >> 5, tc = tid & 31;
    #pragma unroll
    for (int r = 0; r < 32; r += 8) {
        int c = ct0 + tr + r;
        tile[tr + r][tc] = (c < C) ? W[(size_t)c * A_DIM + it0 + tc] : 0.0f;
    }
    __syncthreads();
    #pragma unroll
    for (int r = 0; r < 32; r += 8) {
        int i = it0 + tr + r;
        g_WT[(size_t)i * A_DIM + ct0 + tc] = tile[tc][tr + r];
    }
}

// labels: gridded. Each block redundantly scans the (tiny) detection range for
// a globally consistent dtype verdict, then converts + appends its slice.
// List order within a class is run-varying but consumption is order-independent.
__global__ void k_labels(const int* __restrict__ raw, int n,
                         float* out, int writeLoss) {
    const int tid = threadIdx.x;
    if (blockIdx.x == 0 && tid == 0 && writeLoss) out[0] = 0.0f;
    int nz = 0;
    for (int i = tid; i < n / 2; i += blockDim.x)
        nz |= (raw[2 * i + 1] != 0);
    const bool is32 = (__syncthreads_or(nz) != 0);
    const int stride = gridDim.x * blockDim.x;
    for (int i = blockIdx.x * blockDim.x + tid; i < n; i += stride) {
        int c = is32 ? raw[i] : raw[2 * i];
        g_labels[i] = c;
        int p = atomicAdd(&g_ccount[c], 1);
        g_clist[(size_t)c * MAX_N + p] = i;
    }
}

// ---- fused: v, blocked Cholesky, D/U, in-smem transpose, class solves -------
// (byte-identical to the measured-115.2 round-11 version)
__global__ __launch_bounds__(256, 3)
void k_fused(const float* __restrict__ sigma, const float* __restrict__ W,
             const float* __restrict__ F, const float* __restrict__ mu,
             int C, int K) {
    extern __shared__ float sh[];
    float* sA  = sh;                       // 128 * 132
    float* swl = sA + A_DIM * PITCH;       // 128
    float* sv  = swl + A_DIM;              // 128
    float* srd = sv + A_DIM;               // 128
    float* sdg = srd + A_DIM;              // 128
    float* sD  = sdg + A_DIM;              // 128
    float* sU  = sD + A_DIM;               // 128
    __shared__ float slogdet;

    const int s = blockIdx.x;
    const int cls = s / K;
    const int kk = s - cls * K;
    const int tid = threadIdx.x;
    const int wid = tid >> 5, lane = tid & 31;

    // ---- load Sigma (float4, coalesced), w_l; zero sD ----
    {
        const float4* src4 = reinterpret_cast<const float4*>(sigma + (size_t)s * A_DIM * A_DIM);
        for (int idx = tid; idx < A_DIM * 32; idx += 256) {
            int i = idx >> 5, f = idx & 31;
            *reinterpret_cast<float4*>(&sA[i * PITCH + 4 * f]) = src4[idx];
        }
        if (tid < A_DIM) { swl[tid] = W[cls * A_DIM + tid]; sD[tid] = 0.0f; }
    }
    __syncthreads();

    // ---- v = Sigma @ w_l (before factorization) ----
    if (tid < A_DIM) {
        float acc = 0.0f;
        #pragma unroll 8
        for (int b = 0; b < A_DIM; ++b) acc += sA[b * PITCH + tid] * swl[b];
        sv[tid] = acc;
    }
    __syncthreads();

    // ---- blocked Cholesky (NB = 32) ----
    for (int kb = 0; kb < A_DIM; kb += 32) {
        if (wid == 0) {
            float m[32];
            float* row = &sA[(kb + lane) * PITCH + kb];
            #pragma unroll
            for (int c = 0; c < 32; ++c) m[c] = row[c];
            #pragma unroll
            for (int j = 0; j < 32; ++j) {
                float dj = __shfl_sync(0xffffffffu, m[j], j);
                float l = m[j] * rsqrtf(dj);
                m[j] = l;
                #pragma unroll
                for (int p = j + 1; p < 32; ++p)
                    m[p] -= l * __shfl_sync(0xffffffffu, l, p);
            }
            #pragma unroll
            for (int c = 0; c < 32; ++c)
                if (c <= lane) row[c] = m[c];
            srd[kb + lane] = 1.0f / m[lane];
            sdg[kb + lane] = m[lane];
        }
        __syncthreads();

        const int R = A_DIM - kb - 32;
        if (R > 0) {
            if (tid < R) {
                const int row = kb + 32 + tid;
                float* pr = &sA[row * PITCH + kb];
                const float* pd = &sA[kb * PITCH + kb];
                float x[32];
                #pragma unroll
                for (int c = 0; c < 32; ++c) x[c] = pr[c];
                #pragma unroll
                for (int j = 0; j < 32; ++j) {
                    float a = x[j];
                    #pragma unroll
                    for (int p = 0; p < j; ++p) a -= x[p] * pd[j * PITCH + p];
                    x[j] = a * srd[kb + j];
                }
                #pragma unroll
                for (int c = 0; c < 32; ++c) pr[c] = x[c];
            }
            __syncthreads();

            // SYRK: A22 -= L21 L21^T (lower), 8-col strips
            const int nb = R >> 5;
            const int ntask = 2 * nb * (nb + 1);
            for (int task = wid; task < ntask; task += 8) {
                int b = 0, t = task;
                while (t >= 4 * (b + 1)) { t -= 4 * (b + 1); ++b; }
                const int i  = kb + 32 + 32 * b + lane;
                const int j0 = kb + 32 + 8 * t;
                unsigned long long acc[8];
                #pragma unroll
                for (int q = 0; q < 8; ++q) acc[q] = 0ull;
                const float* pa = &sA[i * PITCH + kb];
                #pragma unroll
                for (int k = 0; k < 32; k += 4) {
                    ulonglong2 av = *reinterpret_cast<const ulonglong2*>(pa + k);
                    #pragma unroll
                    for (int q = 0; q < 8; ++q) {
                        ulonglong2 bv = *reinterpret_cast<const ulonglong2*>(
                            &sA[(j0 + q) * PITCH + kb + k]);
                        fma2(acc[q], av.x, bv.x);
                        fma2(acc[q], av.y, bv.y);
                    }
                }
                #pragma unroll
                for (int q = 0; q < 8; ++q) {
                    int col = j0 + q;
                    if (col <= i) {
                        float2 f = unpack2(acc[q]);
                        sA[i * PITCH + col] -= f.x + f.y;
                    }
                }
            }
            __syncthreads();
        }
    }

    // ---- zero upper triangle; logdet ----
    for (int idx = tid; idx < A_DIM * A_DIM; idx += 256) {
        int j = idx >> 7, i = idx & 127;
        if (i < j) sA[i * PITCH + j] = 0.0f;
    }
    if (tid < 32) {
        float v = logf(sdg[tid]) + logf(sdg[tid + 32]) +
                  logf(sdg[tid + 64]) + logf(sdg[tid + 96]);
        #pragma unroll
        for (int o = 16; o; o >>= 1) v += __shfl_xor_sync(0xffffffffu, v, o);
        if (tid == 0) slogdet = 2.0f * v;
    }
    __syncthreads();

    // ---- D_c = ||L^T w_c||^2 (register-tiled), U_c = v . w_c ----
    for (int g = 0; g < 4; ++g) {
        const int t = (g & 1) ? (7 - wid) : wid;
        const int j0 = 16 * t;
        const int c = 32 * g + lane;
        unsigned long long acc[8];
        #pragma unroll
        for (int q = 0; q < 8; ++q) acc[q] = 0ull;
        float u = 0.0f;
        const bool doU = (t == 0);
        const float* wcol = g_WT + c;

        for (int i = j0; i < A_DIM; ++i) {
            const float* Lr = &sA[i * PITCH + j0];
            float4 L0 = *reinterpret_cast<const float4*>(Lr);
            float4 L1 = *reinterpret_cast<const float4*>(Lr + 4);
            float4 L2 = *reinterpret_cast<const float4*>(Lr + 8);
            float4 L3 = *reinterpret_cast<const float4*>(Lr + 12);
            float wv = wcol[i * A_DIM];
            unsigned long long w2 = pack2(wv, wv);
            fma2(acc[0], pack2(L0.x, L0.y), w2);
            fma2(acc[1], pack2(L0.z, L0.w), w2);
            fma2(acc[2], pack2(L1.x, L1.y), w2);
            fma2(acc[3], pack2(L1.z, L1.w), w2);
            fma2(acc[4], pack2(L2.x, L2.y), w2);
            fma2(acc[5], pack2(L2.z, L2.w), w2);
            fma2(acc[6], pack2(L3.x, L3.y), w2);
            fma2(acc[7], pack2(L3.z, L3.w), w2);
            if (doU) u += sv[i] * wv;
        }
        unsigned long long d2 = 0ull;
        #pragma unroll
        for (int q = 0; q < 8; ++q) fma2(d2, acc[q], acc[q]);
        float2 dd = unpack2(d2);
        atomicAdd(&sD[c], dd.x + dd.y);
        if (doU) sU[c] = u;
    }
    __syncthreads();

    for (int c = tid; c < C; c += 256) {
        g_D[s * A_DIM + c] = sD[c];
        g_U[s * A_DIM + c] = sU[c];
    }

    // ---- transpose lower -> upper (stale lower is dead in the solve) ----
    for (int idx = tid; idx < A_DIM * A_DIM; idx += 256) {
        int i = idx >> 7, j = idx & 127;
        if (i > j) sA[j * PITCH + i] = sA[i * PITCH + j];
    }
    __syncthreads();

    // ---- class-grouped solves: score = dist + logdet, 4 samples per warp ----
    const int cnt = g_ccount[cls];
    const float logd = slogdet;
    const float4* F4 = reinterpret_cast<const float4*>(F);
    const float4 mv = reinterpret_cast<const float4*>(mu)[(size_t)s * 32 + lane];

    for (int m0 = wid * 4; m0 < cnt; m0 += 32) {
        int n[4];
        bool has[4];
        #pragma unroll
        for (int r = 0; r < 4; ++r) {
            has[r] = (m0 + r) < cnt;
            n[r] = g_clist[(size_t)cls * MAX_N + (has[r] ? (m0 + r) : m0)];
        }
        float d[4][4], dist[4];
        #pragma unroll
        for (int r = 0; r < 4; ++r) {
            float4 fv = F4[(size_t)n[r] * 32 + lane];
            d[r][0] = fv.x - mv.x; d[r][1] = fv.y - mv.y;
            d[r][2] = fv.z - mv.z; d[r][3] = fv.w - mv.w;
            dist[r] = 0.0f;
        }
        #pragma unroll 4
        for (int j = 0; j < A_DIM; ++j) {
            float4 col = *reinterpret_cast<const float4*>(&sA[j * PITCH + 4 * lane]);
            float rdj = srd[j];
            int owner = j >> 2, q = j & 3;
            #pragma unroll
            for (int r = 0; r < 4; ++r) {
                float dq = (q == 0) ? d[r][0] : (q == 1) ? d[r][1]
                         : (q == 2) ? d[r][2] : d[r][3];
                float z = __shfl_sync(0xffffffffu, dq, owner) * rdj;
                dist[r] += z * z;
                d[r][0] -= col.x * z;
                d[r][1] -= col.y * z;
                d[r][2] -= col.z * z;
                d[r][3] -= col.w * z;
            }
        }
        if (lane == 0) {
            #pragma unroll
            for (int r = 0; r < 4; ++r)
                if (has[r]) g_score[n[r] * 8 + kk] = dist[r] + logd;
        }
    }
}

// ---------------- fused y = F W^T + b, argmin, aug, log-softmax, loss --------
// De-spilled: outer GEMM loop unroll-limited; aug computed in place in sY.
#define NB 16
#define YT 512
__global__ __launch_bounds__(YT)
void k_yloss(const float* __restrict__ F, const float* __restrict__ W,
             const float* __restrict__ bias, const float* __restrict__ ratioPtr,
             float* __restrict__ yout, float* __restrict__ lossout,
             int N, int C, int K, int writeLoss) {
    extern __shared__ float sh[];
    float* sWT = sh;                       // [128][C]
    float* sF  = sWT + A_DIM * C;          // [NB][128]
    float* sY  = sF + NB * A_DIM;          // [NB][C]  (y, then aug in place)
    float* sB  = sY + NB * C;              // [C]
    const int tid = threadIdx.x;
    const int n0 = blockIdx.x * NB;

    for (int idx = tid; idx < C * A_DIM; idx += YT) {
        int c = idx >> 7, aa = idx & 127;
        sWT[aa * C + c] = W[idx];
    }
    for (int idx = tid; idx < NB * A_DIM; idx += YT) {
        int nl = idx >> 7;
        int n = n0 + nl;
        sF[idx] = (n < N) ? F[(size_t)n * A_DIM + (idx & 127)] : 0.0f;
    }
    for (int c = tid; c < C; c += YT) sB[c] = bias[c];
    __syncthreads();

    const int warp = tid >> 5, lane = tid & 31;
    const int nwarp = YT / 32;             // 16
    const int nchunk = (C + 31) >> 5;

    for (int task = warp; task < NB * nchunk; task += nwarp) {
        int nl = task / nchunk;
        int c = (task - nl * nchunk) * 32 + lane;
        int n = n0 + nl;
        if (c < C && n < N) {
            float acc = sB[c];
            const float* f = sF + nl * A_DIM;
            #pragma unroll 1
            for (int aa = 0; aa < A_DIM; aa += 16) {
                #pragma unroll
                for (int q = 0; q < 16; q += 4) {
                    float4 fv = *reinterpret_cast<const float4*>(f + aa + q);
                    acc += fv.x * sWT[(aa + q) * C + c];
                    acc += fv.y * sWT[(aa + q + 1) * C + c];
                    acc += fv.z * sWT[(aa + q + 2) * C + c];
                    acc += fv.w * sWT[(aa + q + 3) * C + c];
                }
            }
            sY[nl * C + c] = acc;
            yout[(size_t)n * C + c] = acc;
        }
    }
    __syncthreads();

    // epilogue: warp nl handles sample nl; aug written in place in sY
    const float hr = 0.5f * ratioPtr[0];
    const int nl = warp;
    const int n = n0 + nl;
    if (n < N) {
        int l = g_labels[n];
        const float* sc = g_score + n * 8;
        int k = 0;
        float best = sc[0];
        for (int kkk = 1; kkk < K; ++kkk) {
            float v = sc[kkk];
            if (v < best) { best = v; k = kkk; }
        }
        int s = l * K + k;
        const float* Dp = g_D + s * A_DIM;
        const float* Up = g_U + s * A_DIM;
        float ul = Up[l];
        float* aug = sY + nl * C;

        float mymax = -INFINITY;
        for (int m = 0; m < nchunk; ++m) {
            int c = lane + 32 * m;
            if (c < C) {
                float v = aug[c] + hr * (Dp[c] - 2.0f * Up[c] + ul);
                aug[c] = v;
                mymax = fmaxf(mymax, v);
            }
        }
        #pragma unroll
        for (int o = 16; o; o >>= 1)
            mymax = fmaxf(mymax, __shfl_xor_sync(0xffffffffu, mymax, o));
        __syncwarp();
        float sum = 0.0f;
        for (int m = 0; m < nchunk; ++m) {
            int c = lane + 32 * m;
            if (c < C) sum += expf(aug[c] - mymax);
        }
        #pragma unroll
        for (int o = 16; o; o >>= 1) sum += __shfl_xor_sync(0xffffffffu, sum, o);
        if (lane == 0 && writeLoss) {
            float lse = mymax + logf(sum);
            atomicAdd(lossout, (lse - aug[l]) / (float)N);
        }
    }
}

// ---------------- launch -----------------------------------------------------
extern "C" void kernel_launch(void* const* d_in, const int* in_sizes, int n_in,
                              void* d_out, int out_size) {
    const float* F     = (const float*)d_in[0];
    const float* W     = (const float*)d_in[1];
    const float* bias  = (const float*)d_in[2];
    const float* mu    = (const float*)d_in[4];
    const float* sigma = (const float*)d_in[5];
    const int*   lraw  = (const int*)d_in[6];
    const float* ratio = (const float*)d_in[7];

    const int C = in_sizes[2];
    const int K = in_sizes[3] / C;
    const int Ad = in_sizes[1] / C;
    const int N = in_sizes[0] / Ad;
    const int S = C * K;

    float* out = (float*)d_out;
    const int yoff = out_size - N * C;
    const int writeLoss = (yoff >= 1) ? 1 : 0;
    float* yout = out + (yoff > 0 ? yoff : 0);

    const int smem_fused = (A_DIM * PITCH + 6 * A_DIM) * 4;                // 70656
    const int smem_yl    = (A_DIM * C + NB * A_DIM + NB * C + C) * 4;      // 66192

    cudaFuncSetAttribute(k_fused, cudaFuncAttributeMaxDynamicSharedMemorySize, smem_fused);
    cudaFuncSetAttribute(k_yloss, cudaFuncAttributeMaxDynamicSharedMemorySize, smem_yl);

    dim3 wtgrid(4, 4);
    k_wt<<<wtgrid, 256>>>(W, C);                       // also zeroes g_ccount
    k_labels<<<16, 128>>>(lraw, N, out, writeLoss);
    k_fused<<<S, 256, smem_fused>>>(sigma, W, F, mu, C, K);
    k_yloss<<<(N + NB - 1) / NB, YT, smem_yl>>>(F, W, bias, ratio, yout, out,
                                                N, C, K, writeLoss);
}